// round 13
// baseline (speedup 1.0000x reference)
#include <cuda_runtime.h>
#include <math.h>
#include <stdint.h>

#define N_NODES 20000
#define N_EDGES 160000
#define FEAT 576   // 64*1 + 64*3 + 64*5

// ---------------- scratch (device globals, no allocation) ----------------
__device__ __align__(16) float g_cg[11 * 125];              // 11 CG tensors, padded 5x5x5
__device__ __align__(16) float g_up[N_NODES * FEAT];
__device__ __align__(16) float g_skip[N_NODES * FEAT];
__device__ __align__(16) float g_h2[(size_t)N_EDGES * 64];
__device__ __align__(16) float g_w[(size_t)N_EDGES * 704]; // w in [.,704]; TP output reuses first 576
__device__ int g_cnt[N_NODES];
__device__ int g_cur[N_NODES];
__device__ int g_off[N_NODES + 1];
__device__ int g_elist[N_EDGES];

// sorted(set(PATHS)|set(SQ_PATHS)) == PATHS literal order
__constant__ int c_pl1[11] = {0,0,0,1,1,1,1,2,2,2,2};
__constant__ int c_pl2[11] = {0,1,2,0,1,1,2,0,1,2,2};
__constant__ int c_pl3[11] = {0,1,2,1,0,2,1,2,1,0,2};
// Z packing offsets: sizes di*do = {1,3,5,9,3,15,9,25,15,5,25}
__constant__ int c_zoff[12] = {0,1,4,9,18,21,36,45,70,85,90,115};

// ---------------- helpers ----------------
__device__ __forceinline__ float gelu_t(float x) {
    float x3 = x * x * x;
    return 0.5f * x * (1.0f + tanhf(0.7978845608028654f * (x + 0.044715f * x3)));
}

__device__ __forceinline__ void decode_o(int o, int& l, int& v, int& i, int& off, int& d) {
    if (o < 64)       { l = 0; off = 0;   d = 1; v = o;           i = 0; }
    else if (o < 256) { l = 1; off = 64;  d = 3; int r = o - 64;  v = r / 3; i = r - 3 * v; }
    else              { l = 2; off = 256; d = 5; int r = o - 256; v = r / 5; i = r - 5 * v; }
}

// decode a weight-GEMM work item (144 items: (l,i) x 16 v-groups of 4)
__device__ __forceinline__ void decode_item(int item, int& l, int& i, int& vg,
                                            int& off, int& d) {
    if (item < 16)      { l = 0; i = 0; vg = item; off = 0; d = 1; }
    else if (item < 64) { int r = item - 16; l = 1; i = r >> 4; vg = r & 15; off = 64;  d = 3; }
    else                { int r = item - 64; l = 2; i = r >> 4; vg = r & 15; off = 256; d = 5; }
}

__device__ __forceinline__ uint32_t f2tf32(float x) {
    uint32_t r;
    asm("cvt.rna.tf32.f32 %0, %1;" : "=r"(r) : "f"(x));
    return r;
}

// ---------------- CSR build: histogram, scan, scatter ----------------
__global__ void hist_zero() {
    int i = blockIdx.x * 256 + threadIdx.x;
    if (i < N_NODES) { g_cnt[i] = 0; g_cur[i] = 0; }
}
__global__ void hist(const int* __restrict__ recv, int n_edges) {
    int e = blockIdx.x * 256 + threadIdx.x;
    if (e < n_edges) atomicAdd(&g_cnt[recv[e]], 1);
}
__global__ void scan_kernel() {
    // 1024 threads, chunk of 20 each; 2-level shfl scan
    __shared__ int warp_sums[32];
    int t = threadIdx.x;
    int lane = t & 31, wid = t >> 5;
    int base = t * 20;
    int s = 0;
    #pragma unroll 4
    for (int i = 0; i < 20; i++) { int idx = base + i; if (idx < N_NODES) s += g_cnt[idx]; }
    int v = s;
    #pragma unroll
    for (int o = 1; o < 32; o <<= 1) {
        int u = __shfl_up_sync(0xFFFFFFFF, v, o);
        if (lane >= o) v += u;
    }
    if (lane == 31) warp_sums[wid] = v;
    __syncthreads();
    if (wid == 0) {
        int w = warp_sums[lane];
        #pragma unroll
        for (int o = 1; o < 32; o <<= 1) {
            int u = __shfl_up_sync(0xFFFFFFFF, w, o);
            if (lane >= o) w += u;
        }
        warp_sums[lane] = w;
    }
    __syncthreads();
    int run = (wid > 0 ? warp_sums[wid - 1] : 0) + v - s;   // exclusive prefix
    for (int i = 0; i < 20; i++) {
        int idx = base + i;
        if (idx < N_NODES) { g_off[idx] = run; run += g_cnt[idx]; }
    }
    if (t == 1023) g_off[N_NODES] = run;
}
__global__ void scatter_ids(const int* __restrict__ recv, int n_edges) {
    int e = blockIdx.x * 256 + threadIdx.x;
    if (e < n_edges) {
        int r = recv[e];
        int p = atomicAdd(&g_cur[r], 1);
        g_elist[g_off[r] + p] = e;
    }
}

// ---------------- CG computation (exact port of reference) ----------------
__device__ double dfact(int n) {
    double r = 1.0;
    for (int i = 2; i <= n; i++) r *= (double)i;
    return r;
}

__device__ double clebsch_d(int j1, int m1, int j2, int m2, int j3, int m3) {
    if (m1 + m2 != m3) return 0.0;
    double pref = sqrt((2.0 * j3 + 1.0) * dfact(j3 + j1 - j2) * dfact(j3 - j1 + j2) *
                       dfact(j1 + j2 - j3) / dfact(j1 + j2 + j3 + 1));
    pref *= sqrt(dfact(j3 + m3) * dfact(j3 - m3) * dfact(j1 - m1) * dfact(j1 + m1) *
                 dfact(j2 - m2) * dfact(j2 + m2));
    double s = 0.0;
    for (int k = 0; k <= j1 + j2 - j3; k++) {
        int d0 = k, d1 = j1 + j2 - j3 - k, d2 = j1 - m1 - k;
        int d3 = j2 + m2 - k, d4 = j3 - j2 + m1 + k, d5 = j3 - j1 - m2 + k;
        if (d0 < 0 || d1 < 0 || d2 < 0 || d3 < 0 || d4 < 0 || d5 < 0) continue;
        double den = dfact(d0) * dfact(d1) * dfact(d2) * dfact(d3) * dfact(d4) * dfact(d5);
        s += ((k & 1) ? -1.0 : 1.0) / den;
    }
    return pref * s;
}

__device__ void u_real_entry(int l, int a, int i, double& re, double& im) {
    re = 0.0; im = 0.0;
    const double r2inv = 0.7071067811865475244;
    if (a == l) { if (i == l) re = 1.0; return; }
    if (a > l) {
        int m = a - l;
        if (i == l + m)      re = ((m & 1) ? -1.0 : 1.0) * r2inv;
        else if (i == l - m) re = r2inv;
    } else {
        int m = l - a;
        if (i == l - m)      im = r2inv;
        else if (i == l + m) im = -((m & 1) ? -1.0 : 1.0) * r2inv;
    }
}

__global__ void cg_kernel() {
    int p = blockIdx.x;
    int l1 = c_pl1[p], l2 = c_pl2[p], l3 = c_pl3[p];
    int d1 = 2 * l1 + 1, d2 = 2 * l2 + 1, d3 = 2 * l3 + 1;
    int ne = d1 * d2 * d3;
    __shared__ double Rr[125], Ri[125];
    __shared__ double s_inv;
    __shared__ int s_useR;
    int t = threadIdx.x;

    for (int e = t; e < 125; e += blockDim.x) g_cg[p * 125 + e] = 0.0f;

    for (int e = t; e < ne; e += blockDim.x) {
        int a = e / (d2 * d3);
        int rem = e - a * d2 * d3;
        int b = rem / d3;
        int c = rem - b * d3;
        double sr = 0.0, si = 0.0;
        for (int i = 0; i < d1; i++) {
            for (int j = 0; j < d2; j++) {
                int m1 = i - l1, m2 = j - l2, m3 = m1 + m2;
                if (m3 < -l3 || m3 > l3) continue;
                int kk = m3 + l3;
                double cc = clebsch_d(l1, m1, l2, m2, l3, m3);
                if (cc == 0.0) continue;
                double u1r, u1i, u2r, u2i, u3r, u3i;
                u_real_entry(l1, a, i, u1r, u1i);
                u_real_entry(l2, b, j, u2r, u2i);
                u_real_entry(l3, c, kk, u3r, u3i);
                u3i = -u3i;
                double pr = u1r * u2r - u1i * u2i;
                double pq = u1r * u2i + u1i * u2r;
                double qr = pr * u3r - pq * u3i;
                double qi = pr * u3i + pq * u3r;
                sr += qr * cc;
                si += qi * cc;
            }
        }
        Rr[e] = sr; Ri[e] = si;
    }
    __syncthreads();
    if (t == 0) {
        double a2 = 0.0, b2 = 0.0;
        for (int e = 0; e < ne; e++) { a2 += Rr[e] * Rr[e]; b2 += Ri[e] * Ri[e]; }
        int useR = sqrt(a2) >= sqrt(b2);
        s_useR = useR;
        s_inv = 1.0 / sqrt(useR ? a2 : b2);
    }
    __syncthreads();
    for (int e = t; e < ne; e += blockDim.x) {
        int a = e / (d2 * d3);
        int rem = e - a * d2 * d3;
        int b = rem / d3;
        int c = rem - b * d3;
        double val = (s_useR ? Rr[e] : Ri[e]) * s_inv;
        g_cg[p * 125 + (a * 5 + b) * 5 + c] = (float)val;
    }
}

// ---------------- node pre: up, skip ----------------
__global__ void node_pre(const float* __restrict__ node_feats,
                         const float* __restrict__ W_up,
                         const float* __restrict__ W_skip,
                         const int* __restrict__ specie) {
    const int NT = 160;
    int n = blockIdx.x;
    int t = threadIdx.x;
    __shared__ __align__(16) float sh_nf[FEAT];
    __shared__ __align__(16) float sh_up[FEAT];
    __shared__ __align__(16) float sh_sk[FEAT];

    const float4* row4 = (const float4*)(node_feats + (size_t)n * FEAT);
    for (int i = t; i < 144; i += NT) ((float4*)sh_nf)[i] = row4[i];
    __syncthreads();
    int sp = specie[n];
    for (int item = t; item < 144; item += NT) {
        int l, i, vg, off, d;
        decode_item(item, l, i, vg, off, d);
        const float4* Wu4 = (const float4*)(W_up + l * 4096) + vg;
        const float4* Ws4 = (const float4*)(W_skip + ((size_t)sp * 3 + l) * 4096) + vg;
        float4 au = make_float4(0.f,0.f,0.f,0.f);
        float4 as_ = make_float4(0.f,0.f,0.f,0.f);
        const float* nfp = sh_nf + off + i;
        #pragma unroll 8
        for (int u = 0; u < 64; u++) {
            float f = nfp[u * d];
            float4 wu = Wu4[u * 16];
            float4 ws = Ws4[u * 16];
            au.x += f * wu.x; au.y += f * wu.y; au.z += f * wu.z; au.w += f * wu.w;
            as_.x += f * ws.x; as_.y += f * ws.y; as_.z += f * ws.z; as_.w += f * ws.w;
        }
        int v0 = vg * 4;
        sh_up[off + (v0+0)*d + i] = au.x * 0.125f;
        sh_up[off + (v0+1)*d + i] = au.y * 0.125f;
        sh_up[off + (v0+2)*d + i] = au.z * 0.125f;
        sh_up[off + (v0+3)*d + i] = au.w * 0.125f;
        sh_sk[off + (v0+0)*d + i] = as_.x * 0.125f;
        sh_sk[off + (v0+1)*d + i] = as_.y * 0.125f;
        sh_sk[off + (v0+2)*d + i] = as_.z * 0.125f;
        sh_sk[off + (v0+3)*d + i] = as_.w * 0.125f;
    }
    __syncthreads();
    float4* up4 = (float4*)(g_up + (size_t)n * FEAT);
    float4* sk4 = (float4*)(g_skip + (size_t)n * FEAT);
    for (int i = t; i < 144; i += NT) {
        up4[i] = ((float4*)sh_up)[i];
        sk4[i] = ((float4*)sh_sk)[i];
    }
}

// ---------------- edge basis: bessel/env -> h1 -> h2 (32 edges/block) ----------------
__global__ void edge_basis(const float* __restrict__ vectors,
                           const float* __restrict__ M1,
                           const float* __restrict__ M2) {
    int E0 = blockIdx.x * 32;
    int t = threadIdx.x;
    __shared__ float s_len[32], s_coef[32];
    __shared__ float s_r[32][8];
    __shared__ float s_h1[32][64];

    if (t < 32) {
        int e = E0 + t;
        float vx = vectors[3*e], vy = vectors[3*e+1], vz = vectors[3*e+2];
        float len = sqrtf(vx*vx + vy*vy + vz*vz);
        float safe = (len == 0.0f) ? 1.0f : len;
        float env = 0.0f;
        if (len < 1.0f) {
            float dnm = fminf(len*len - 1.0f, -1e-6f);
            env = expf(2.0f * len * len / dnm);
        }
        s_len[t] = len;
        s_coef[t] = 1.4142135623730951f * env / safe;
    }
    __syncthreads();
    {
        int e = t >> 3, nb = t & 7;   // 256 threads == 32*8
        s_r[e][nb] = s_coef[e] * sinf(3.14159265358979323846f * (float)(nb+1) * s_len[e]);
    }
    __syncthreads();
    for (int idx = t; idx < 2048; idx += 256) {
        int e = idx >> 6, o = idx & 63;
        float acc = 0.0f;
        #pragma unroll
        for (int nb = 0; nb < 8; nb++) acc += s_r[e][nb] * M1[nb*64 + o];
        s_h1[e][o] = gelu_t(acc * 0.3535533905932738f);
    }
    __syncthreads();
    for (int idx = t; idx < 2048; idx += 256) {
        int e = idx >> 6, o = idx & 63;
        float acc = 0.0f;
        #pragma unroll 8
        for (int k = 0; k < 64; k++) acc += s_h1[e][k] * M2[k*64 + o];
        float h2 = gelu_t(acc * 0.125f);
        if (s_len[e] == 0.0f) h2 = 0.0f;   // zero-length edge -> mix = 0
        g_h2[(size_t)(E0 + e) * 64 + o] = h2;
    }
}

// ---------------- w GEMM (TF32 tensor cores), o-chunk loop inside ----------------
// w[e,704] = h2[e,64] @ M3[64,704] * 0.125
__global__ void w_gemm_tf32(const float* __restrict__ M3) {
    int e0 = blockIdx.x * 64;
    int t = threadIdx.x;
    int wi = t >> 5;
    int lane = t & 31;
    int g = lane >> 2;       // group id 0..7
    int c = lane & 3;        // thread-in-group 0..3

    __shared__ __align__(16) uint32_t s_a[64][68];  // h2 tf32 [e][k], stride 68
    __shared__ __align__(16) uint32_t s_b[64][72];  // M3 tf32 chunk [k][o], stride 72

    // load h2 tile once
    #pragma unroll
    for (int it = 0; it < 8; it++) {
        int idx = t + it * 128;
        int e = idx >> 4, k4 = idx & 15;
        float4 v = ((const float4*)(g_h2 + (size_t)(e0 + e) * 64))[k4];
        uint32_t* dst = &s_a[e][k4 * 4];
        dst[0] = f2tf32(v.x); dst[1] = f2tf32(v.y);
        dst[2] = f2tf32(v.z); dst[3] = f2tf32(v.w);
    }

    int eb = wi * 16;
    for (int oc = 0; oc < 11; oc++) {
        int o0 = oc * 64;
        if (oc > 0) __syncthreads();   // previous chunk's s_b reads done
        #pragma unroll
        for (int it = 0; it < 8; it++) {
            int idx = t + it * 128;
            int k = idx >> 4, o4 = idx & 15;
            float4 v = ((const float4*)(M3 + (size_t)k * 704 + o0))[o4];
            uint32_t* dst = &s_b[k][o4 * 4];
            dst[0] = f2tf32(v.x); dst[1] = f2tf32(v.y);
            dst[2] = f2tf32(v.z); dst[3] = f2tf32(v.w);
        }
        __syncthreads();               // s_b (and s_a on first iter) ready

        float acc[8][4];
        #pragma unroll
        for (int nt = 0; nt < 8; nt++)
            #pragma unroll
            for (int q = 0; q < 4; q++) acc[nt][q] = 0.0f;

        #pragma unroll
        for (int ks = 0; ks < 8; ks++) {
            int kb = ks * 8;
            uint32_t a0 = s_a[eb + g][kb + c];
            uint32_t a1 = s_a[eb + g + 8][kb + c];
            uint32_t a2 = s_a[eb + g][kb + c + 4];
            uint32_t a3 = s_a[eb + g + 8][kb + c + 4];
            #pragma unroll
            for (int nt = 0; nt < 8; nt++) {
                uint32_t b0 = s_b[kb + c][nt * 8 + g];
                uint32_t b1 = s_b[kb + c + 4][nt * 8 + g];
                asm volatile(
                    "mma.sync.aligned.m16n8k8.row.col.f32.tf32.tf32.f32 "
                    "{%0,%1,%2,%3}, {%4,%5,%6,%7}, {%8,%9}, {%0,%1,%2,%3};"
                    : "+f"(acc[nt][0]), "+f"(acc[nt][1]), "+f"(acc[nt][2]), "+f"(acc[nt][3])
                    : "r"(a0), "r"(a1), "r"(a2), "r"(a3), "r"(b0), "r"(b1));
            }
        }

        int er0 = e0 + eb + g;
        int er1 = er0 + 8;
        #pragma unroll
        for (int nt = 0; nt < 8; nt++) {
            int col = o0 + nt * 8 + 2 * c;
            float2 v0 = make_float2(acc[nt][0] * 0.125f, acc[nt][1] * 0.125f);
            float2 v1 = make_float2(acc[nt][2] * 0.125f, acc[nt][3] * 0.125f);
            *(float2*)(g_w + (size_t)er0 * 704 + col) = v0;
            *(float2*)(g_w + (size_t)er1 * 704 + col) = v1;
        }
    }
}

// ---------------- edge TP v3: same-edge v-pairing; Z loads CSE'd in registers ----------------
// Output: first 576 floats of each g_w row (in-place; all reads precede writes via barrier).
__global__ void edge_tp(const float* __restrict__ vectors,
                        const int* __restrict__ senders) {
    const int EPB = 8;
    int E0 = blockIdx.x * EPB;
    int t = threadIdx.x;
    __shared__ __align__(16) float s_cg[1375];
    __shared__ __align__(16) float s_msg[EPB][576];
    __shared__ __align__(16) float s_Z[EPB][116];
    __shared__ float s_Y[EPB][9];
    __shared__ int s_send[EPB];

    if (t < EPB) {
        int e = E0 + t;
        s_send[t] = senders[e];
        float vx = vectors[3*e], vy = vectors[3*e+1], vz = vectors[3*e+2];
        float len = sqrtf(vx*vx + vy*vy + vz*vz);
        float il = 1.0f / fmaxf(len, 1e-9f);
        float dx = vx*il, dy = vy*il, dz = vz*il;
        const float SQ3 = 1.7320508075688772f;
        const float SQ15 = 3.872983346207417f;
        s_Y[t][0] = 1.0f;
        s_Y[t][1] = SQ3 * dy; s_Y[t][2] = SQ3 * dz; s_Y[t][3] = SQ3 * dx;
        s_Y[t][4] = SQ15 * dx * dy;
        s_Y[t][5] = SQ15 * dy * dz;
        s_Y[t][6] = 1.118033988749895f * (3.0f * dz * dz - 1.0f);
        s_Y[t][7] = SQ15 * dx * dz;
        s_Y[t][8] = 1.9364916731037085f * (dx * dx - dy * dy);
    }
    for (int i = t; i < 1375; i += 256) s_cg[i] = g_cg[i];
    __syncthreads();

    // gather msg (float4)
    for (int idx = t; idx < EPB * 144; idx += 256) {
        int e = idx / 144, q = idx - 144 * e;
        ((float4*)s_msg[e])[q] = ((const float4*)(g_up + (size_t)s_send[e] * FEAT))[q];
    }
    __syncthreads();

    // Z[p][i][k] = sum_j Y[j] * cg[p][i][j][k]  (115 packed entries per edge)
    for (int idx = t; idx < EPB * 115; idx += 256) {
        int e = idx / 115, r = idx - 115 * e;
        int p = 0;
        while (r >= c_zoff[p + 1]) p++;
        int rr = r - c_zoff[p];
        int lf = c_pl2[p], lo = c_pl3[p];
        int dO = 2*lo + 1, dj = 2*lf + 1;
        int i = rr / dO, k = rr - dO * i;
        int yo = (lf == 0) ? 0 : ((lf == 1) ? 1 : 4);
        const float* cgp = s_cg + p*125 + i*25 + k;
        float acc = 0.0f;
        for (int j = 0; j < dj; j++) acc += s_Y[e][yo + j] * cgp[j*5];
        s_Z[e][r] = acc;
    }
    __syncthreads();

    // TP: thread t handles edge t>>5, v = (t&31) and (t&31)+32.
    // Same-edge pairing -> constant-index Z loads CSE across both items.
    float o0[2], o1[2][3], o2[2][5];
    {
        int e = t >> 5;
        int vbase = t & 31;
        const float* M = s_msg[e];
        const float* Z = s_Z[e];
        #pragma unroll
        for (int it = 0; it < 2; it++) {
            int v = vbase + it * 32;
            const float* Wg = g_w + (size_t)(E0 + e) * 704 + v;

            float m0 = M[v];
            float m1a = M[64 + v*3], m1b = M[64 + v*3 + 1], m1c = M[64 + v*3 + 2];
            float m2a = M[256 + v*5], m2b = M[256 + v*5 + 1], m2c = M[256 + v*5 + 2];
            float m2d = M[256 + v*5 + 3], m2e = M[256 + v*5 + 4];

            float w0  = Wg[0*64], w1 = Wg[1*64], w2 = Wg[2*64], w3 = Wg[3*64];
            float w4  = Wg[4*64], w5 = Wg[5*64], w6 = Wg[6*64], w7 = Wg[7*64];
            float w8  = Wg[8*64], w9 = Wg[9*64], w10 = Wg[10*64];

            // lo=0
            {
                float in0 = m0 * Z[0];
                float in4 = m1a*Z[18] + m1b*Z[19] + m1c*Z[20];
                float in9 = m2a*Z[85] + m2b*Z[86] + m2c*Z[87] + m2d*Z[88] + m2e*Z[89];
                o0[it] = w0*in0 + w4*in4 + w9*in9;
            }
            // lo=1, k=0..2
            #pragma unroll
            for (int k = 0; k < 3; k++) {
                float in1 = m0 * Z[1 + k];
                float in3 = m1a*Z[9+k]  + m1b*Z[12+k] + m1c*Z[15+k];
                float in6 = m1a*Z[36+k] + m1b*Z[39+k] + m1c*Z[42+k];
                float in8 = m2a*Z[70+k] + m2b*Z[73+k] + m2c*Z[76+k]
                          + m2d*Z[79+k] + m2e*Z[82+k];
                o1[it][k] = w1*in1 + w3*in3 + w6*in6 + w8*in8;
            }
            // lo=2, k=0..4
            #pragma unroll
            for (int k = 0; k < 5; k++) {
                float in2  = m0 * Z[4 + k];
                float in5  = m1a*Z[21+k] + m1b*Z[26+k] + m1c*Z[31+k];
                float in7  = m2a*Z[45+k] + m2b*Z[50+k] + m2c*Z[55+k]
                           + m2d*Z[60+k] + m2e*Z[65+k];
                float in10 = m2a*Z[90+k] + m2b*Z[95+k] + m2c*Z[100+k]
                           + m2d*Z[105+k] + m2e*Z[110+k];
                o2[it][k] = w2*in2 + w5*in5 + w7*in7 + w10*in10;
            }
        }
    }
    __syncthreads();   // all g_w reads complete before in-place writes

    {
        int e = t >> 5;
        int vbase = t & 31;
        float* row = g_w + (size_t)(E0 + e) * 704;
        #pragma unroll
        for (int it = 0; it < 2; it++) {
            int v = vbase + it * 32;
            row[v] = o0[it];
            #pragma unroll
            for (int k = 0; k < 3; k++) row[64 + v*3 + k] = o1[it][k];
            #pragma unroll
            for (int k = 0; k < 5; k++) row[256 + v*5 + k] = o2[it][k];
        }
    }
}

// ---------------- node post: 2 nodes/block; CSR gather, dn, squares, W_out, softnorm ----------------
#define NPB 2
__global__ void node_post(const float* __restrict__ W_down,
                          const float* __restrict__ W_out0,
                          const float* __restrict__ W_out1,
                          const float* __restrict__ W_out2,
                          float* __restrict__ out) {
    const int NT = 160;
    int n0 = blockIdx.x * NPB;
    int t = threadIdx.x;
    __shared__ __align__(16) float sh_agg[NPB][FEAT];
    __shared__ __align__(16) float sh_dn[NPB][FEAT];
    __shared__ __align__(16) float sh_cat0[NPB][256];
    __shared__ __align__(16) float sh_cat1[NPB][576];
    __shared__ __align__(16) float sh_cat2[NPB][1280];
    __shared__ __align__(16) float sh_o[NPB][FEAT];
    __shared__ __align__(16) float s_cg[1375];

    // CSR gather: agg[nn] = sum of TP outputs over incoming edges
    for (int i = t; i < 144 * NPB; i += NT) {
        int nn = i / 144, q = i - 144 * nn;
        int n = n0 + nn;
        int beg = g_off[n], end = g_off[n + 1];
        float4 a = make_float4(0.f, 0.f, 0.f, 0.f);
        for (int d = beg; d < end; d++) {
            int eid = g_elist[d];
            float4 v = ((const float4*)(g_w + (size_t)eid * 704))[q];
            a.x += v.x; a.y += v.y; a.z += v.z; a.w += v.w;
        }
        ((float4*)sh_agg[nn])[q] = a;
    }
    for (int i = t; i < 1375; i += NT) s_cg[i] = g_cg[i];
    __syncthreads();

    // dn = (agg/sqrt(8)) @ W_down / sqrt(64); gelu on l=0
    const float dn_scale = 0.125f * 0.3535533905932738f;
    for (int item = t; item < 144; item += NT) {
        int l, i, vg, off, d;
        decode_item(item, l, i, vg, off, d);
        const float4* W4 = (const float4*)(W_down + l * 4096) + vg;
        float4 acc[NPB];
        #pragma unroll
        for (int nn = 0; nn < NPB; nn++) acc[nn] = make_float4(0.f,0.f,0.f,0.f);
        #pragma unroll 4
        for (int u = 0; u < 64; u++) {
            float4 w = W4[u * 16];
            #pragma unroll
            for (int nn = 0; nn < NPB; nn++) {
                float f = sh_agg[nn][off + u * d + i];
                acc[nn].x += f*w.x; acc[nn].y += f*w.y;
                acc[nn].z += f*w.z; acc[nn].w += f*w.w;
            }
        }
        int v0 = vg * 4;
        #pragma unroll
        for (int nn = 0; nn < NPB; nn++) {
            float4 a = acc[nn];
            a.x *= dn_scale; a.y *= dn_scale; a.z *= dn_scale; a.w *= dn_scale;
            if (l == 0) { a.x = gelu_t(a.x); a.y = gelu_t(a.y); a.z = gelu_t(a.z); a.w = gelu_t(a.w); }
            sh_dn[nn][off + (v0+0)*d + i] = a.x;
            sh_dn[nn][off + (v0+1)*d + i] = a.y;
            sh_dn[nn][off + (v0+2)*d + i] = a.z;
            sh_dn[nn][off + (v0+3)*d + i] = a.w;
        }
    }
    __syncthreads();

    // cat dn parts
    for (int i = t; i < 64 * NPB; i += NT)  { int nn = i >> 6, r = i & 63; sh_cat0[nn][r] = sh_dn[nn][r]; }
    for (int i = t; i < 192 * NPB; i += NT) { int nn = i / 192, r = i - 192*nn; sh_cat1[nn][r] = sh_dn[nn][64 + r]; }
    for (int i = t; i < 320 * NPB; i += NT) { int nn = i / 320, r = i - 320*nn; sh_cat2[nn][r] = sh_dn[nn][256 + r]; }

    // squares
    {
        const int sq_cg[8]  = {0, 4, 9, 1, 6, 2, 5, 10};
        const int sq_lA[8]  = {0, 1, 2, 0, 1, 0, 1, 2};
        const int sq_lB[8]  = {0, 1, 2, 1, 2, 2, 1, 2};
        const int sq_lO[8]  = {0, 0, 0, 1, 1, 2, 2, 2};
        const int sq_blk[8] = {1, 2, 3, 1, 2, 1, 2, 3};
        const int loff[3] = {0, 64, 256};
        #pragma unroll
        for (int sp = 0; sp < 8; sp++) {
            int lA = sq_lA[sp], lB = sq_lB[sp], lO = sq_lO[sp];
            int dA = 2*lA+1, dB = 2*lB+1, dO = 2*lO+1;
            int offA = loff[lA], offB = loff[lB];
            const float* cgp = s_cg + sq_cg[sp] * 125;
            int nout = 64 * dO;
            int blk = sq_blk[sp];
            for (int idx = t; idx < nout; idx += NT) {
                int u = idx / dO, k = idx - dO * u;
                float accs[NPB] = {0.f, 0.f};
                #pragma unroll
                for (int i = 0; i < dA; i++) {
                    #pragma unroll
                    for (int j = 0; j < dB; j++) {
                        float cgv = cgp[(i*5 + j)*5 + k];
                        #pragma unroll
                        for (int nn = 0; nn < NPB; nn++)
                            accs[nn] += sh_dn[nn][offA + u*dA + i]
                                      * sh_dn[nn][offB + u*dB + j] * cgv;
                    }
                }
                #pragma unroll
                for (int nn = 0; nn < NPB; nn++) {
                    if (lO == 0)      sh_cat0[nn][blk*64 + u] = accs[nn];
                    else if (lO == 1) sh_cat1[nn][(blk*64 + u)*3 + k] = accs[nn];
                    else              sh_cat2[nn][(blk*64 + u)*5 + k] = accs[nn];
                }
            }
        }
    }
    __syncthreads();

    // output linears (weight float4 shared across NPB nodes)
    for (int item = t; item < 144; item += NT) {
        int l, i, vg, off, d;
        decode_item(item, l, i, vg, off, d);
        float4 acc[NPB];
        #pragma unroll
        for (int nn = 0; nn < NPB; nn++) acc[nn] = make_float4(0.f,0.f,0.f,0.f);
        float scale;
        if (l == 0) {
            const float4* W4 = (const float4*)W_out0 + vg;
            #pragma unroll 4
            for (int u = 0; u < 256; u++) {
                float4 w = W4[u * 16];
                #pragma unroll
                for (int nn = 0; nn < NPB; nn++) {
                    float f = sh_cat0[nn][u];
                    acc[nn].x += f*w.x; acc[nn].y += f*w.y;
                    acc[nn].z += f*w.z; acc[nn].w += f*w.w;
                }
            }
            scale = 0.0625f;
        } else if (l == 1) {
            const float4* W4 = (const float4*)W_out1 + vg;
            #pragma unroll 4
            for (int u = 0; u < 192; u++) {
                float4 w = W4[u * 16];
                #pragma unroll
                for (int nn = 0; nn < NPB; nn++) {
                    float f = sh_cat1[nn][u*3 + i];
                    acc[nn].x += f*w.x; acc[nn].y += f*w.y;
                    acc[nn].z += f*w.z; acc[nn].w += f*w.w;
                }
            }
            scale = 0.07216878364870323f;
        } else {
            const float4* W4 = (const float4*)W_out2 + vg;
            #pragma unroll 4
            for (int u = 0; u < 256; u++) {
                float4 w = W4[u * 16];
                #pragma unroll
                for (int nn = 0; nn < NPB; nn++) {
                    float f = sh_cat2[nn][u*5 + i];
                    acc[nn].x += f*w.x; acc[nn].y += f*w.y;
                    acc[nn].z += f*w.z; acc[nn].w += f*w.w;
                }
            }
            scale = 0.0625f;
        }
        int v0 = vg * 4;
        #pragma unroll
        for (int nn = 0; nn < NPB; nn++) {
            sh_o[nn][off + (v0+0)*d + i] = acc[nn].x * scale;
            sh_o[nn][off + (v0+1)*d + i] = acc[nn].y * scale;
            sh_o[nn][off + (v0+2)*d + i] = acc[nn].z * scale;
            sh_o[nn][off + (v0+3)*d + i] = acc[nn].w * scale;
        }
    }
    __syncthreads();

    // soft norm + final
    for (int idx = t; idx < FEAT * NPB; idx += NT) {
        int nn = idx / FEAT, o = idx - FEAT * nn;
        int l, v, i, off, d;
        decode_o(o, l, v, i, off, d);
        float s2 = 0.0f;
        for (int j = 0; j < d; j++) { float q = sh_o[nn][off + v*d + j]; s2 += q*q; }
        float nrm = sqrtf(s2) * 1e-5f;
        float sus = (nrm > 0.0f) ? expf(-1.0f / nrm) : 0.0f;
        float ob = sh_o[nn][o] / (1.0f + nrm * sus);
        int n = n0 + nn;
        out[(size_t)n * FEAT + o] = 0.9f * g_skip[(size_t)n * FEAT + o] + 0.45f * ob;
    }
}

// ---------------- launch ----------------
extern "C" void kernel_launch(void* const* d_in, const int* in_sizes, int n_in,
                              void* d_out, int out_size) {
    const float* vectors    = (const float*)d_in[0];
    const float* node_feats = (const float*)d_in[1];
    const float* W_up       = (const float*)d_in[2];
    const float* W_skip     = (const float*)d_in[3];
    const float* M1         = (const float*)d_in[4];
    const float* M2         = (const float*)d_in[5];
    const float* M3         = (const float*)d_in[6];
    const float* W_out0     = (const float*)d_in[7];
    const float* W_out1     = (const float*)d_in[8];
    const float* W_out2     = (const float*)d_in[9];
    const float* W_down     = (const float*)d_in[10];
    const int*   specie     = (const int*)d_in[11];
    const int*   senders    = (const int*)d_in[12];
    const int*   receivers  = (const int*)d_in[13];

    int n_nodes = in_sizes[11];
    int n_edges = in_sizes[12];

    cg_kernel<<<11, 128>>>();
    hist_zero<<<(n_nodes + 255) / 256, 256>>>();
    hist<<<(n_edges + 255) / 256, 256>>>(receivers, n_edges);
    scan_kernel<<<1, 1024>>>();
    scatter_ids<<<(n_edges + 255) / 256, 256>>>(receivers, n_edges);
    node_pre<<<n_nodes, 160>>>(node_feats, W_up, W_skip, specie);
    edge_basis<<<n_edges / 32, 256>>>(vectors, M1, M2);
    w_gemm_tf32<<<n_edges / 64, 128>>>(M3);
    edge_tp<<<n_edges / 8, 256>>>(vectors, senders);
    node_post<<<n_nodes / NPB, 160>>>(W_down, W_out0, W_out1, W_out2, (float*)d_out);
}

// round 14
// speedup vs baseline: 1.0971x; 1.0971x over previous
#include <cuda_runtime.h>
#include <math.h>
#include <stdint.h>

#define N_NODES 20000
#define N_EDGES 160000
#define FEAT 576   // 64*1 + 64*3 + 64*5

// ---------------- scratch (device globals, no allocation) ----------------
__device__ __align__(16) float g_cg[11 * 125];              // 11 CG tensors, padded 5x5x5
__device__ __align__(16) float g_up[N_NODES * FEAT];
__device__ __align__(16) float g_skip[N_NODES * FEAT];
__device__ __align__(16) float g_h2[(size_t)N_EDGES * 64];
__device__ __align__(16) float g_w[(size_t)N_EDGES * 704]; // w in [.,704]; TP output reuses first 576
__device__ __align__(16) uint32_t g_m3t[64 * 704];          // M3 pre-converted to tf32
__device__ int g_cnt[N_NODES];
__device__ int g_cur[N_NODES];
__device__ int g_off[N_NODES + 1];
__device__ int g_elist[N_EDGES];

// sorted(set(PATHS)|set(SQ_PATHS)) == PATHS literal order
__constant__ int c_pl1[11] = {0,0,0,1,1,1,1,2,2,2,2};
__constant__ int c_pl2[11] = {0,1,2,0,1,1,2,0,1,2,2};
__constant__ int c_pl3[11] = {0,1,2,1,0,2,1,2,1,0,2};
// Z packing offsets: sizes di*do = {1,3,5,9,3,15,9,25,15,5,25}
__constant__ int c_zoff[12] = {0,1,4,9,18,21,36,45,70,85,90,115};

// ---------------- helpers ----------------
__device__ __forceinline__ float gelu_t(float x) {
    float x3 = x * x * x;
    return 0.5f * x * (1.0f + tanhf(0.7978845608028654f * (x + 0.044715f * x3)));
}

__device__ __forceinline__ void decode_o(int o, int& l, int& v, int& i, int& off, int& d) {
    if (o < 64)       { l = 0; off = 0;   d = 1; v = o;           i = 0; }
    else if (o < 256) { l = 1; off = 64;  d = 3; int r = o - 64;  v = r / 3; i = r - 3 * v; }
    else              { l = 2; off = 256; d = 5; int r = o - 256; v = r / 5; i = r - 5 * v; }
}

// decode a weight-GEMM work item (144 items: (l,i) x 16 v-groups of 4)
__device__ __forceinline__ void decode_item(int item, int& l, int& i, int& vg,
                                            int& off, int& d) {
    if (item < 16)      { l = 0; i = 0; vg = item; off = 0; d = 1; }
    else if (item < 64) { int r = item - 16; l = 1; i = r >> 4; vg = r & 15; off = 64;  d = 3; }
    else                { int r = item - 64; l = 2; i = r >> 4; vg = r & 15; off = 256; d = 5; }
}

__device__ __forceinline__ uint32_t f2tf32(float x) {
    uint32_t r;
    asm("cvt.rna.tf32.f32 %0, %1;" : "=r"(r) : "f"(x));
    return r;
}

// ---------------- M3 tf32 pre-conversion ----------------
__global__ void m3_convert(const float* __restrict__ M3) {
    int i = blockIdx.x * 256 + threadIdx.x;
    if (i < 64 * 704) g_m3t[i] = f2tf32(M3[i]);
}

// ---------------- CSR build: histogram, scan, scatter ----------------
__global__ void hist_zero() {
    int i = blockIdx.x * 256 + threadIdx.x;
    if (i < N_NODES) { g_cnt[i] = 0; g_cur[i] = 0; }
}
__global__ void hist(const int* __restrict__ recv, int n_edges) {
    int e = blockIdx.x * 256 + threadIdx.x;
    if (e < n_edges) atomicAdd(&g_cnt[recv[e]], 1);
}
__global__ void scan_kernel() {
    // 1024 threads, chunk of 20 each; 2-level shfl scan
    __shared__ int warp_sums[32];
    int t = threadIdx.x;
    int lane = t & 31, wid = t >> 5;
    int base = t * 20;
    int s = 0;
    #pragma unroll 4
    for (int i = 0; i < 20; i++) { int idx = base + i; if (idx < N_NODES) s += g_cnt[idx]; }
    int v = s;
    #pragma unroll
    for (int o = 1; o < 32; o <<= 1) {
        int u = __shfl_up_sync(0xFFFFFFFF, v, o);
        if (lane >= o) v += u;
    }
    if (lane == 31) warp_sums[wid] = v;
    __syncthreads();
    if (wid == 0) {
        int w = warp_sums[lane];
        #pragma unroll
        for (int o = 1; o < 32; o <<= 1) {
            int u = __shfl_up_sync(0xFFFFFFFF, w, o);
            if (lane >= o) w += u;
        }
        warp_sums[lane] = w;
    }
    __syncthreads();
    int run = (wid > 0 ? warp_sums[wid - 1] : 0) + v - s;   // exclusive prefix
    for (int i = 0; i < 20; i++) {
        int idx = base + i;
        if (idx < N_NODES) { g_off[idx] = run; run += g_cnt[idx]; }
    }
    if (t == 1023) g_off[N_NODES] = run;
}
__global__ void scatter_ids(const int* __restrict__ recv, int n_edges) {
    int e = blockIdx.x * 256 + threadIdx.x;
    if (e < n_edges) {
        int r = recv[e];
        int p = atomicAdd(&g_cur[r], 1);
        g_elist[g_off[r] + p] = e;
    }
}

// ---------------- CG computation (exact port of reference) ----------------
__device__ double dfact(int n) {
    double r = 1.0;
    for (int i = 2; i <= n; i++) r *= (double)i;
    return r;
}

__device__ double clebsch_d(int j1, int m1, int j2, int m2, int j3, int m3) {
    if (m1 + m2 != m3) return 0.0;
    double pref = sqrt((2.0 * j3 + 1.0) * dfact(j3 + j1 - j2) * dfact(j3 - j1 + j2) *
                       dfact(j1 + j2 - j3) / dfact(j1 + j2 + j3 + 1));
    pref *= sqrt(dfact(j3 + m3) * dfact(j3 - m3) * dfact(j1 - m1) * dfact(j1 + m1) *
                 dfact(j2 - m2) * dfact(j2 + m2));
    double s = 0.0;
    for (int k = 0; k <= j1 + j2 - j3; k++) {
        int d0 = k, d1 = j1 + j2 - j3 - k, d2 = j1 - m1 - k;
        int d3 = j2 + m2 - k, d4 = j3 - j2 + m1 + k, d5 = j3 - j1 - m2 + k;
        if (d0 < 0 || d1 < 0 || d2 < 0 || d3 < 0 || d4 < 0 || d5 < 0) continue;
        double den = dfact(d0) * dfact(d1) * dfact(d2) * dfact(d3) * dfact(d4) * dfact(d5);
        s += ((k & 1) ? -1.0 : 1.0) / den;
    }
    return pref * s;
}

__device__ void u_real_entry(int l, int a, int i, double& re, double& im) {
    re = 0.0; im = 0.0;
    const double r2inv = 0.7071067811865475244;
    if (a == l) { if (i == l) re = 1.0; return; }
    if (a > l) {
        int m = a - l;
        if (i == l + m)      re = ((m & 1) ? -1.0 : 1.0) * r2inv;
        else if (i == l - m) re = r2inv;
    } else {
        int m = l - a;
        if (i == l - m)      im = r2inv;
        else if (i == l + m) im = -((m & 1) ? -1.0 : 1.0) * r2inv;
    }
}

__global__ void cg_kernel() {
    int p = blockIdx.x;
    int l1 = c_pl1[p], l2 = c_pl2[p], l3 = c_pl3[p];
    int d1 = 2 * l1 + 1, d2 = 2 * l2 + 1, d3 = 2 * l3 + 1;
    int ne = d1 * d2 * d3;
    __shared__ double Rr[125], Ri[125];
    __shared__ double s_inv;
    __shared__ int s_useR;
    int t = threadIdx.x;

    for (int e = t; e < 125; e += blockDim.x) g_cg[p * 125 + e] = 0.0f;

    for (int e = t; e < ne; e += blockDim.x) {
        int a = e / (d2 * d3);
        int rem = e - a * d2 * d3;
        int b = rem / d3;
        int c = rem - b * d3;
        double sr = 0.0, si = 0.0;
        for (int i = 0; i < d1; i++) {
            for (int j = 0; j < d2; j++) {
                int m1 = i - l1, m2 = j - l2, m3 = m1 + m2;
                if (m3 < -l3 || m3 > l3) continue;
                int kk = m3 + l3;
                double cc = clebsch_d(l1, m1, l2, m2, l3, m3);
                if (cc == 0.0) continue;
                double u1r, u1i, u2r, u2i, u3r, u3i;
                u_real_entry(l1, a, i, u1r, u1i);
                u_real_entry(l2, b, j, u2r, u2i);
                u_real_entry(l3, c, kk, u3r, u3i);
                u3i = -u3i;
                double pr = u1r * u2r - u1i * u2i;
                double pq = u1r * u2i + u1i * u2r;
                double qr = pr * u3r - pq * u3i;
                double qi = pr * u3i + pq * u3r;
                sr += qr * cc;
                si += qi * cc;
            }
        }
        Rr[e] = sr; Ri[e] = si;
    }
    __syncthreads();
    if (t == 0) {
        double a2 = 0.0, b2 = 0.0;
        for (int e = 0; e < ne; e++) { a2 += Rr[e] * Rr[e]; b2 += Ri[e] * Ri[e]; }
        int useR = sqrt(a2) >= sqrt(b2);
        s_useR = useR;
        s_inv = 1.0 / sqrt(useR ? a2 : b2);
    }
    __syncthreads();
    for (int e = t; e < ne; e += blockDim.x) {
        int a = e / (d2 * d3);
        int rem = e - a * d2 * d3;
        int b = rem / d3;
        int c = rem - b * d3;
        double val = (s_useR ? Rr[e] : Ri[e]) * s_inv;
        g_cg[p * 125 + (a * 5 + b) * 5 + c] = (float)val;
    }
}

// ---------------- node pre: up, skip ----------------
__global__ void node_pre(const float* __restrict__ node_feats,
                         const float* __restrict__ W_up,
                         const float* __restrict__ W_skip,
                         const int* __restrict__ specie) {
    const int NT = 160;
    int n = blockIdx.x;
    int t = threadIdx.x;
    __shared__ __align__(16) float sh_nf[FEAT];
    __shared__ __align__(16) float sh_up[FEAT];
    __shared__ __align__(16) float sh_sk[FEAT];

    const float4* row4 = (const float4*)(node_feats + (size_t)n * FEAT);
    for (int i = t; i < 144; i += NT) ((float4*)sh_nf)[i] = row4[i];
    __syncthreads();
    int sp = specie[n];
    for (int item = t; item < 144; item += NT) {
        int l, i, vg, off, d;
        decode_item(item, l, i, vg, off, d);
        const float4* Wu4 = (const float4*)(W_up + l * 4096) + vg;
        const float4* Ws4 = (const float4*)(W_skip + ((size_t)sp * 3 + l) * 4096) + vg;
        float4 au = make_float4(0.f,0.f,0.f,0.f);
        float4 as_ = make_float4(0.f,0.f,0.f,0.f);
        const float* nfp = sh_nf + off + i;
        #pragma unroll 8
        for (int u = 0; u < 64; u++) {
            float f = nfp[u * d];
            float4 wu = Wu4[u * 16];
            float4 ws = Ws4[u * 16];
            au.x += f * wu.x; au.y += f * wu.y; au.z += f * wu.z; au.w += f * wu.w;
            as_.x += f * ws.x; as_.y += f * ws.y; as_.z += f * ws.z; as_.w += f * ws.w;
        }
        int v0 = vg * 4;
        sh_up[off + (v0+0)*d + i] = au.x * 0.125f;
        sh_up[off + (v0+1)*d + i] = au.y * 0.125f;
        sh_up[off + (v0+2)*d + i] = au.z * 0.125f;
        sh_up[off + (v0+3)*d + i] = au.w * 0.125f;
        sh_sk[off + (v0+0)*d + i] = as_.x * 0.125f;
        sh_sk[off + (v0+1)*d + i] = as_.y * 0.125f;
        sh_sk[off + (v0+2)*d + i] = as_.z * 0.125f;
        sh_sk[off + (v0+3)*d + i] = as_.w * 0.125f;
    }
    __syncthreads();
    float4* up4 = (float4*)(g_up + (size_t)n * FEAT);
    float4* sk4 = (float4*)(g_skip + (size_t)n * FEAT);
    for (int i = t; i < 144; i += NT) {
        up4[i] = ((float4*)sh_up)[i];
        sk4[i] = ((float4*)sh_sk)[i];
    }
}

// ---------------- edge basis: bessel/env -> h1 -> h2 (32 edges/block) ----------------
__global__ void edge_basis(const float* __restrict__ vectors,
                           const float* __restrict__ M1,
                           const float* __restrict__ M2) {
    int E0 = blockIdx.x * 32;
    int t = threadIdx.x;
    __shared__ float s_len[32], s_coef[32];
    __shared__ float s_r[32][8];
    __shared__ float s_h1[32][64];

    if (t < 32) {
        int e = E0 + t;
        float vx = vectors[3*e], vy = vectors[3*e+1], vz = vectors[3*e+2];
        float len = sqrtf(vx*vx + vy*vy + vz*vz);
        float safe = (len == 0.0f) ? 1.0f : len;
        float env = 0.0f;
        if (len < 1.0f) {
            float dnm = fminf(len*len - 1.0f, -1e-6f);
            env = expf(2.0f * len * len / dnm);
        }
        s_len[t] = len;
        s_coef[t] = 1.4142135623730951f * env / safe;
    }
    __syncthreads();
    {
        int e = t >> 3, nb = t & 7;   // 256 threads == 32*8
        s_r[e][nb] = s_coef[e] * sinf(3.14159265358979323846f * (float)(nb+1) * s_len[e]);
    }
    __syncthreads();
    for (int idx = t; idx < 2048; idx += 256) {
        int e = idx >> 6, o = idx & 63;
        float acc = 0.0f;
        #pragma unroll
        for (int nb = 0; nb < 8; nb++) acc += s_r[e][nb] * M1[nb*64 + o];
        s_h1[e][o] = gelu_t(acc * 0.3535533905932738f);
    }
    __syncthreads();
    for (int idx = t; idx < 2048; idx += 256) {
        int e = idx >> 6, o = idx & 63;
        float acc = 0.0f;
        #pragma unroll 8
        for (int k = 0; k < 64; k++) acc += s_h1[e][k] * M2[k*64 + o];
        float h2 = gelu_t(acc * 0.125f);
        if (s_len[e] == 0.0f) h2 = 0.0f;   // zero-length edge -> mix = 0
        g_h2[(size_t)(E0 + e) * 64 + o] = h2;
    }
}

// ---------------- w GEMM (TF32 tensor cores), o-chunk loop inside ----------------
// w[e,704] = h2[e,64] @ M3[64,704] * 0.125 ; M3 pre-converted in g_m3t
__global__ void w_gemm_tf32() {
    int e0 = blockIdx.x * 64;
    int t = threadIdx.x;
    int wi = t >> 5;
    int lane = t & 31;
    int g = lane >> 2;       // group id 0..7
    int c = lane & 3;        // thread-in-group 0..3

    __shared__ __align__(16) uint32_t s_a[64][68];  // h2 tf32 [e][k], stride 68
    __shared__ __align__(16) uint32_t s_b[64][72];  // M3 tf32 chunk [k][o], stride 72

    // load h2 tile once
    #pragma unroll
    for (int it = 0; it < 8; it++) {
        int idx = t + it * 128;
        int e = idx >> 4, k4 = idx & 15;
        float4 v = ((const float4*)(g_h2 + (size_t)(e0 + e) * 64))[k4];
        uint32_t* dst = &s_a[e][k4 * 4];
        dst[0] = f2tf32(v.x); dst[1] = f2tf32(v.y);
        dst[2] = f2tf32(v.z); dst[3] = f2tf32(v.w);
    }

    int eb = wi * 16;
    for (int oc = 0; oc < 11; oc++) {
        int o0 = oc * 64;
        if (oc > 0) __syncthreads();   // previous chunk's s_b reads done
        #pragma unroll
        for (int it = 0; it < 8; it++) {
            int idx = t + it * 128;
            int k = idx >> 4, o4 = idx & 15;
            uint4 v = ((const uint4*)(g_m3t + (size_t)k * 704 + o0))[o4];
            *(uint4*)&s_b[k][o4 * 4] = v;
        }
        __syncthreads();               // s_b (and s_a on first iter) ready

        float acc[8][4];
        #pragma unroll
        for (int nt = 0; nt < 8; nt++)
            #pragma unroll
            for (int q = 0; q < 4; q++) acc[nt][q] = 0.0f;

        #pragma unroll
        for (int ks = 0; ks < 8; ks++) {
            int kb = ks * 8;
            uint32_t a0 = s_a[eb + g][kb + c];
            uint32_t a1 = s_a[eb + g + 8][kb + c];
            uint32_t a2 = s_a[eb + g][kb + c + 4];
            uint32_t a3 = s_a[eb + g + 8][kb + c + 4];
            #pragma unroll
            for (int nt = 0; nt < 8; nt++) {
                uint32_t b0 = s_b[kb + c][nt * 8 + g];
                uint32_t b1 = s_b[kb + c + 4][nt * 8 + g];
                asm volatile(
                    "mma.sync.aligned.m16n8k8.row.col.f32.tf32.tf32.f32 "
                    "{%0,%1,%2,%3}, {%4,%5,%6,%7}, {%8,%9}, {%0,%1,%2,%3};"
                    : "+f"(acc[nt][0]), "+f"(acc[nt][1]), "+f"(acc[nt][2]), "+f"(acc[nt][3])
                    : "r"(a0), "r"(a1), "r"(a2), "r"(a3), "r"(b0), "r"(b1));
            }
        }

        int er0 = e0 + eb + g;
        int er1 = er0 + 8;
        #pragma unroll
        for (int nt = 0; nt < 8; nt++) {
            int col = o0 + nt * 8 + 2 * c;
            float2 v0 = make_float2(acc[nt][0] * 0.125f, acc[nt][1] * 0.125f);
            float2 v1 = make_float2(acc[nt][2] * 0.125f, acc[nt][3] * 0.125f);
            *(float2*)(g_w + (size_t)er0 * 704 + col) = v0;
            *(float2*)(g_w + (size_t)er1 * 704 + col) = v1;
        }
    }
}

// ---------------- edge TP (R12 version): thread-per-(edge,v); Z broadcast; W in registers ----------------
// Output: first 576 floats of each g_w row (in-place; all reads precede writes via barrier).
__global__ void edge_tp(const float* __restrict__ vectors,
                        const int* __restrict__ senders) {
    const int EPB = 8;
    int E0 = blockIdx.x * EPB;
    int t = threadIdx.x;
    __shared__ __align__(16) float s_cg[1375];
    __shared__ __align__(16) float s_msg[EPB][576];
    __shared__ __align__(16) float s_Z[EPB][116];
    __shared__ float s_Y[EPB][9];
    __shared__ int s_send[EPB];

    if (t < EPB) {
        int e = E0 + t;
        s_send[t] = senders[e];
        float vx = vectors[3*e], vy = vectors[3*e+1], vz = vectors[3*e+2];
        float len = sqrtf(vx*vx + vy*vy + vz*vz);
        float il = 1.0f / fmaxf(len, 1e-9f);
        float dx = vx*il, dy = vy*il, dz = vz*il;
        const float SQ3 = 1.7320508075688772f;
        const float SQ15 = 3.872983346207417f;
        s_Y[t][0] = 1.0f;
        s_Y[t][1] = SQ3 * dy; s_Y[t][2] = SQ3 * dz; s_Y[t][3] = SQ3 * dx;
        s_Y[t][4] = SQ15 * dx * dy;
        s_Y[t][5] = SQ15 * dy * dz;
        s_Y[t][6] = 1.118033988749895f * (3.0f * dz * dz - 1.0f);
        s_Y[t][7] = SQ15 * dx * dz;
        s_Y[t][8] = 1.9364916731037085f * (dx * dx - dy * dy);
    }
    for (int i = t; i < 1375; i += 256) s_cg[i] = g_cg[i];
    __syncthreads();

    // gather msg (float4)
    for (int idx = t; idx < EPB * 144; idx += 256) {
        int e = idx / 144, q = idx - 144 * e;
        ((float4*)s_msg[e])[q] = ((const float4*)(g_up + (size_t)s_send[e] * FEAT))[q];
    }
    __syncthreads();

    // Z[p][i][k] = sum_j Y[j] * cg[p][i][j][k]  (115 packed entries per edge)
    for (int idx = t; idx < EPB * 115; idx += 256) {
        int e = idx / 115, r = idx - 115 * e;
        int p = 0;
        while (r >= c_zoff[p + 1]) p++;
        int rr = r - c_zoff[p];
        int lf = c_pl2[p], lo = c_pl3[p];
        int dO = 2*lo + 1, dj = 2*lf + 1;
        int i = rr / dO, k = rr - dO * i;
        int yo = (lf == 0) ? 0 : ((lf == 1) ? 1 : 4);
        const float* cgp = s_cg + p*125 + i*25 + k;
        float acc = 0.0f;
        for (int j = 0; j < dj; j++) acc += s_Y[e][yo + j] * cgp[j*5];
        s_Z[e][r] = acc;
    }
    __syncthreads();

    // TP: 2 items per thread (512 = 8 edges x 64 v). Warp = 32 consecutive v of one edge
    float o0[2], o1[2][3], o2[2][5];
    #pragma unroll
    for (int it = 0; it < 2; it++) {
        int idx = t + it * 256;
        int e = idx >> 6, v = idx & 63;
        const float* M = s_msg[e];
        const float* Z = s_Z[e];
        const float* Wg = g_w + (size_t)(E0 + e) * 704 + v;

        float m0 = M[v];
        float m1a = M[64 + v*3], m1b = M[64 + v*3 + 1], m1c = M[64 + v*3 + 2];
        float m2a = M[256 + v*5], m2b = M[256 + v*5 + 1], m2c = M[256 + v*5 + 2];
        float m2d = M[256 + v*5 + 3], m2e = M[256 + v*5 + 4];

        float w0  = Wg[0*64], w1 = Wg[1*64], w2 = Wg[2*64], w3 = Wg[3*64];
        float w4  = Wg[4*64], w5 = Wg[5*64], w6 = Wg[6*64], w7 = Wg[7*64];
        float w8  = Wg[8*64], w9 = Wg[9*64], w10 = Wg[10*64];

        // lo=0
        {
            float in0 = m0 * Z[0];
            float in4 = m1a*Z[18] + m1b*Z[19] + m1c*Z[20];
            float in9 = m2a*Z[85] + m2b*Z[86] + m2c*Z[87] + m2d*Z[88] + m2e*Z[89];
            o0[it] = w0*in0 + w4*in4 + w9*in9;
        }
        // lo=1, k=0..2
        #pragma unroll
        for (int k = 0; k < 3; k++) {
            float in1 = m0 * Z[1 + k];
            float in3 = m1a*Z[9+k]  + m1b*Z[12+k] + m1c*Z[15+k];
            float in6 = m1a*Z[36+k] + m1b*Z[39+k] + m1c*Z[42+k];
            float in8 = m2a*Z[70+k] + m2b*Z[73+k] + m2c*Z[76+k]
                      + m2d*Z[79+k] + m2e*Z[82+k];
            o1[it][k] = w1*in1 + w3*in3 + w6*in6 + w8*in8;
        }
        // lo=2, k=0..4
        #pragma unroll
        for (int k = 0; k < 5; k++) {
            float in2  = m0 * Z[4 + k];
            float in5  = m1a*Z[21+k] + m1b*Z[26+k] + m1c*Z[31+k];
            float in7  = m2a*Z[45+k] + m2b*Z[50+k] + m2c*Z[55+k]
                       + m2d*Z[60+k] + m2e*Z[65+k];
            float in10 = m2a*Z[90+k] + m2b*Z[95+k] + m2c*Z[100+k]
                       + m2d*Z[105+k] + m2e*Z[110+k];
            o2[it][k] = w2*in2 + w5*in5 + w7*in7 + w10*in10;
        }
    }
    __syncthreads();   // all g_w reads complete before in-place writes

    #pragma unroll
    for (int it = 0; it < 2; it++) {
        int idx = t + it * 256;
        int e = idx >> 6, v = idx & 63;
        float* row = g_w + (size_t)(E0 + e) * 704;
        row[v] = o0[it];
        #pragma unroll
        for (int k = 0; k < 3; k++) row[64 + v*3 + k] = o1[it][k];
        #pragma unroll
        for (int k = 0; k < 5; k++) row[256 + v*5 + k] = o2[it][k];
    }
}

// ---------------- node post: 2 nodes/block; CSR gather, dn, squares, W_out, softnorm ----------------
#define NPB 2
__global__ void node_post(const float* __restrict__ W_down,
                          const float* __restrict__ W_out0,
                          const float* __restrict__ W_out1,
                          const float* __restrict__ W_out2,
                          float* __restrict__ out) {
    const int NT = 160;
    int n0 = blockIdx.x * NPB;
    int t = threadIdx.x;
    __shared__ __align__(16) float sh_agg[NPB][FEAT];
    __shared__ __align__(16) float sh_dn[NPB][FEAT];
    __shared__ __align__(16) float sh_cat0[NPB][256];
    __shared__ __align__(16) float sh_cat1[NPB][576];
    __shared__ __align__(16) float sh_cat2[NPB][1280];
    __shared__ __align__(16) float sh_o[NPB][FEAT];
    __shared__ __align__(16) float s_cg[1375];

    // CSR gather: agg[nn] = sum of TP outputs over incoming edges
    for (int i = t; i < 144 * NPB; i += NT) {
        int nn = i / 144, q = i - 144 * nn;
        int n = n0 + nn;
        int beg = g_off[n], end = g_off[n + 1];
        float4 a = make_float4(0.f, 0.f, 0.f, 0.f);
        for (int d = beg; d < end; d++) {
            int eid = g_elist[d];
            float4 v = ((const float4*)(g_w + (size_t)eid * 704))[q];
            a.x += v.x; a.y += v.y; a.z += v.z; a.w += v.w;
        }
        ((float4*)sh_agg[nn])[q] = a;
    }
    for (int i = t; i < 1375; i += NT) s_cg[i] = g_cg[i];
    __syncthreads();

    // dn = (agg/sqrt(8)) @ W_down / sqrt(64); gelu on l=0
    const float dn_scale = 0.125f * 0.3535533905932738f;
    for (int item = t; item < 144; item += NT) {
        int l, i, vg, off, d;
        decode_item(item, l, i, vg, off, d);
        const float4* W4 = (const float4*)(W_down + l * 4096) + vg;
        float4 acc[NPB];
        #pragma unroll
        for (int nn = 0; nn < NPB; nn++) acc[nn] = make_float4(0.f,0.f,0.f,0.f);
        #pragma unroll 4
        for (int u = 0; u < 64; u++) {
            float4 w = W4[u * 16];
            #pragma unroll
            for (int nn = 0; nn < NPB; nn++) {
                float f = sh_agg[nn][off + u * d + i];
                acc[nn].x += f*w.x; acc[nn].y += f*w.y;
                acc[nn].z += f*w.z; acc[nn].w += f*w.w;
            }
        }
        int v0 = vg * 4;
        #pragma unroll
        for (int nn = 0; nn < NPB; nn++) {
            float4 a = acc[nn];
            a.x *= dn_scale; a.y *= dn_scale; a.z *= dn_scale; a.w *= dn_scale;
            if (l == 0) { a.x = gelu_t(a.x); a.y = gelu_t(a.y); a.z = gelu_t(a.z); a.w = gelu_t(a.w); }
            sh_dn[nn][off + (v0+0)*d + i] = a.x;
            sh_dn[nn][off + (v0+1)*d + i] = a.y;
            sh_dn[nn][off + (v0+2)*d + i] = a.z;
            sh_dn[nn][off + (v0+3)*d + i] = a.w;
        }
    }
    __syncthreads();

    // cat dn parts
    for (int i = t; i < 64 * NPB; i += NT)  { int nn = i >> 6, r = i & 63; sh_cat0[nn][r] = sh_dn[nn][r]; }
    for (int i = t; i < 192 * NPB; i += NT) { int nn = i / 192, r = i - 192*nn; sh_cat1[nn][r] = sh_dn[nn][64 + r]; }
    for (int i = t; i < 320 * NPB; i += NT) { int nn = i / 320, r = i - 320*nn; sh_cat2[nn][r] = sh_dn[nn][256 + r]; }

    // squares
    {
        const int sq_cg[8]  = {0, 4, 9, 1, 6, 2, 5, 10};
        const int sq_lA[8]  = {0, 1, 2, 0, 1, 0, 1, 2};
        const int sq_lB[8]  = {0, 1, 2, 1, 2, 2, 1, 2};
        const int sq_lO[8]  = {0, 0, 0, 1, 1, 2, 2, 2};
        const int sq_blk[8] = {1, 2, 3, 1, 2, 1, 2, 3};
        const int loff[3] = {0, 64, 256};
        #pragma unroll
        for (int sp = 0; sp < 8; sp++) {
            int lA = sq_lA[sp], lB = sq_lB[sp], lO = sq_lO[sp];
            int dA = 2*lA+1, dB = 2*lB+1, dO = 2*lO+1;
            int offA = loff[lA], offB = loff[lB];
            const float* cgp = s_cg + sq_cg[sp] * 125;
            int nout = 64 * dO;
            int blk = sq_blk[sp];
            for (int idx = t; idx < nout; idx += NT) {
                int u = idx / dO, k = idx - dO * u;
                float accs[NPB] = {0.f, 0.f};
                #pragma unroll
                for (int i = 0; i < dA; i++) {
                    #pragma unroll
                    for (int j = 0; j < dB; j++) {
                        float cgv = cgp[(i*5 + j)*5 + k];
                        #pragma unroll
                        for (int nn = 0; nn < NPB; nn++)
                            accs[nn] += sh_dn[nn][offA + u*dA + i]
                                      * sh_dn[nn][offB + u*dB + j] * cgv;
                    }
                }
                #pragma unroll
                for (int nn = 0; nn < NPB; nn++) {
                    if (lO == 0)      sh_cat0[nn][blk*64 + u] = accs[nn];
                    else if (lO == 1) sh_cat1[nn][(blk*64 + u)*3 + k] = accs[nn];
                    else              sh_cat2[nn][(blk*64 + u)*5 + k] = accs[nn];
                }
            }
        }
    }
    __syncthreads();

    // output linears (weight float4 shared across NPB nodes)
    for (int item = t; item < 144; item += NT) {
        int l, i, vg, off, d;
        decode_item(item, l, i, vg, off, d);
        float4 acc[NPB];
        #pragma unroll
        for (int nn = 0; nn < NPB; nn++) acc[nn] = make_float4(0.f,0.f,0.f,0.f);
        float scale;
        if (l == 0) {
            const float4* W4 = (const float4*)W_out0 + vg;
            #pragma unroll 4
            for (int u = 0; u < 256; u++) {
                float4 w = W4[u * 16];
                #pragma unroll
                for (int nn = 0; nn < NPB; nn++) {
                    float f = sh_cat0[nn][u];
                    acc[nn].x += f*w.x; acc[nn].y += f*w.y;
                    acc[nn].z += f*w.z; acc[nn].w += f*w.w;
                }
            }
            scale = 0.0625f;
        } else if (l == 1) {
            const float4* W4 = (const float4*)W_out1 + vg;
            #pragma unroll 4
            for (int u = 0; u < 192; u++) {
                float4 w = W4[u * 16];
                #pragma unroll
                for (int nn = 0; nn < NPB; nn++) {
                    float f = sh_cat1[nn][u*3 + i];
                    acc[nn].x += f*w.x; acc[nn].y += f*w.y;
                    acc[nn].z += f*w.z; acc[nn].w += f*w.w;
                }
            }
            scale = 0.07216878364870323f;
        } else {
            const float4* W4 = (const float4*)W_out2 + vg;
            #pragma unroll 4
            for (int u = 0; u < 256; u++) {
                float4 w = W4[u * 16];
                #pragma unroll
                for (int nn = 0; nn < NPB; nn++) {
                    float f = sh_cat2[nn][u*5 + i];
                    acc[nn].x += f*w.x; acc[nn].y += f*w.y;
                    acc[nn].z += f*w.z; acc[nn].w += f*w.w;
                }
            }
            scale = 0.0625f;
        }
        int v0 = vg * 4;
        #pragma unroll
        for (int nn = 0; nn < NPB; nn++) {
            sh_o[nn][off + (v0+0)*d + i] = acc[nn].x * scale;
            sh_o[nn][off + (v0+1)*d + i] = acc[nn].y * scale;
            sh_o[nn][off + (v0+2)*d + i] = acc[nn].z * scale;
            sh_o[nn][off + (v0+3)*d + i] = acc[nn].w * scale;
        }
    }
    __syncthreads();

    // soft norm + final
    for (int idx = t; idx < FEAT * NPB; idx += NT) {
        int nn = idx / FEAT, o = idx - FEAT * nn;
        int l, v, i, off, d;
        decode_o(o, l, v, i, off, d);
        float s2 = 0.0f;
        for (int j = 0; j < d; j++) { float q = sh_o[nn][off + v*d + j]; s2 += q*q; }
        float nrm = sqrtf(s2) * 1e-5f;
        float sus = (nrm > 0.0f) ? expf(-1.0f / nrm) : 0.0f;
        float ob = sh_o[nn][o] / (1.0f + nrm * sus);
        int n = n0 + nn;
        out[(size_t)n * FEAT + o] = 0.9f * g_skip[(size_t)n * FEAT + o] + 0.45f * ob;
    }
}

// ---------------- launch ----------------
extern "C" void kernel_launch(void* const* d_in, const int* in_sizes, int n_in,
                              void* d_out, int out_size) {
    const float* vectors    = (const float*)d_in[0];
    const float* node_feats = (const float*)d_in[1];
    const float* W_up       = (const float*)d_in[2];
    const float* W_skip     = (const float*)d_in[3];
    const float* M1         = (const float*)d_in[4];
    const float* M2         = (const float*)d_in[5];
    const float* M3         = (const float*)d_in[6];
    const float* W_out0     = (const float*)d_in[7];
    const float* W_out1     = (const float*)d_in[8];
    const float* W_out2     = (const float*)d_in[9];
    const float* W_down     = (const float*)d_in[10];
    const int*   specie     = (const int*)d_in[11];
    const int*   senders    = (const int*)d_in[12];
    const int*   receivers  = (const int*)d_in[13];

    int n_nodes = in_sizes[11];
    int n_edges = in_sizes[12];

    cg_kernel<<<11, 128>>>();
    m3_convert<<<(64 * 704 + 255) / 256, 256>>>(M3);
    hist_zero<<<(n_nodes + 255) / 256, 256>>>();
    hist<<<(n_edges + 255) / 256, 256>>>(receivers, n_edges);
    scan_kernel<<<1, 1024>>>();
    scatter_ids<<<(n_edges + 255) / 256, 256>>>(receivers, n_edges);
    node_pre<<<n_nodes, 160>>>(node_feats, W_up, W_skip, specie);
    edge_basis<<<n_edges / 32, 256>>>(vectors, M1, M2);
    w_gemm_tf32<<<n_edges / 64, 128>>>();
    edge_tp<<<n_edges / 8, 256>>>(vectors, senders);
    node_post<<<n_nodes / NPB, 160>>>(W_down, W_out0, W_out1, W_out2, (float*)d_out);
}

// round 15
// speedup vs baseline: 1.3041x; 1.1886x over previous
#include <cuda_runtime.h>
#include <math.h>
#include <stdint.h>

#define N_NODES 20000
#define N_EDGES 160000
#define FEAT 576   // 64*1 + 64*3 + 64*5

// ---------------- scratch (device globals, no allocation) ----------------
__device__ __align__(16) float g_cg[11 * 125];
__device__ __align__(16) float g_up[N_NODES * FEAT];
__device__ __align__(16) float g_skip[N_NODES * FEAT];
__device__ __align__(16) float g_h2[(size_t)N_EDGES * 64];
__device__ __align__(16) float g_w[(size_t)N_EDGES * 704]; // w; TP output reuses first 576
__device__ __align__(16) uint32_t g_m3t[64 * 704];          // M3 tf32
__device__ __align__(16) uint32_t g_wt[45056];              // W_out0|1|2 tf32 (16384|12288|16384)
__device__ __align__(16) float g_cat0[(size_t)N_NODES * 256];
__device__ __align__(16) float g_cat1[(size_t)N_NODES * 3 * 192];
__device__ __align__(16) float g_cat2[(size_t)N_NODES * 5 * 256];
__device__ __align__(16) float g_o[(size_t)N_NODES * FEAT];
__device__ int g_cnt[N_NODES];
__device__ int g_cur[N_NODES];
__device__ int g_off[N_NODES + 1];
__device__ int g_elist[N_EDGES];

__constant__ int c_pl1[11] = {0,0,0,1,1,1,1,2,2,2,2};
__constant__ int c_pl2[11] = {0,1,2,0,1,1,2,0,1,2,2};
__constant__ int c_pl3[11] = {0,1,2,1,0,2,1,2,1,0,2};
__constant__ int c_zoff[12] = {0,1,4,9,18,21,36,45,70,85,90,115};

// ---------------- helpers ----------------
__device__ __forceinline__ float gelu_t(float x) {
    float x3 = x * x * x;
    return 0.5f * x * (1.0f + tanhf(0.7978845608028654f * (x + 0.044715f * x3)));
}

__device__ __forceinline__ void decode_item(int item, int& l, int& i, int& vg,
                                            int& off, int& d) {
    if (item < 16)      { l = 0; i = 0; vg = item; off = 0; d = 1; }
    else if (item < 64) { int r = item - 16; l = 1; i = r >> 4; vg = r & 15; off = 64;  d = 3; }
    else                { int r = item - 64; l = 2; i = r >> 4; vg = r & 15; off = 256; d = 5; }
}

__device__ __forceinline__ uint32_t f2tf32(float x) {
    uint32_t r;
    asm("cvt.rna.tf32.f32 %0, %1;" : "=r"(r) : "f"(x));
    return r;
}

// ---------------- weight tf32 pre-conversion ----------------
__global__ void m3_convert(const float* __restrict__ M3) {
    int i = blockIdx.x * 256 + threadIdx.x;
    if (i < 64 * 704) g_m3t[i] = f2tf32(M3[i]);
}
__global__ void wout_convert(const float* __restrict__ W0,
                             const float* __restrict__ W1,
                             const float* __restrict__ W2) {
    int i = blockIdx.x * 256 + threadIdx.x;
    if (i < 16384)       g_wt[i] = f2tf32(W0[i]);
    else if (i < 28672)  g_wt[i] = f2tf32(W1[i - 16384]);
    else if (i < 45056)  g_wt[i] = f2tf32(W2[i - 28672]);
}

// ---------------- CSR build ----------------
__global__ void hist_zero() {
    int i = blockIdx.x * 256 + threadIdx.x;
    if (i < N_NODES) { g_cnt[i] = 0; g_cur[i] = 0; }
}
__global__ void hist(const int* __restrict__ recv, int n_edges) {
    int e = blockIdx.x * 256 + threadIdx.x;
    if (e < n_edges) atomicAdd(&g_cnt[recv[e]], 1);
}
__global__ void scan_kernel() {
    __shared__ int warp_sums[32];
    int t = threadIdx.x;
    int lane = t & 31, wid = t >> 5;
    int base = t * 20;
    int s = 0;
    #pragma unroll 4
    for (int i = 0; i < 20; i++) { int idx = base + i; if (idx < N_NODES) s += g_cnt[idx]; }
    int v = s;
    #pragma unroll
    for (int o = 1; o < 32; o <<= 1) {
        int u = __shfl_up_sync(0xFFFFFFFF, v, o);
        if (lane >= o) v += u;
    }
    if (lane == 31) warp_sums[wid] = v;
    __syncthreads();
    if (wid == 0) {
        int w = warp_sums[lane];
        #pragma unroll
        for (int o = 1; o < 32; o <<= 1) {
            int u = __shfl_up_sync(0xFFFFFFFF, w, o);
            if (lane >= o) w += u;
        }
        warp_sums[lane] = w;
    }
    __syncthreads();
    int run = (wid > 0 ? warp_sums[wid - 1] : 0) + v - s;
    for (int i = 0; i < 20; i++) {
        int idx = base + i;
        if (idx < N_NODES) { g_off[idx] = run; run += g_cnt[idx]; }
    }
    if (t == 1023) g_off[N_NODES] = run;
}
__global__ void scatter_ids(const int* __restrict__ recv, int n_edges) {
    int e = blockIdx.x * 256 + threadIdx.x;
    if (e < n_edges) {
        int r = recv[e];
        int p = atomicAdd(&g_cur[r], 1);
        g_elist[g_off[r] + p] = e;
    }
}

// ---------------- CG computation (exact port of reference) ----------------
__device__ double dfact(int n) {
    double r = 1.0;
    for (int i = 2; i <= n; i++) r *= (double)i;
    return r;
}

__device__ double clebsch_d(int j1, int m1, int j2, int m2, int j3, int m3) {
    if (m1 + m2 != m3) return 0.0;
    double pref = sqrt((2.0 * j3 + 1.0) * dfact(j3 + j1 - j2) * dfact(j3 - j1 + j2) *
                       dfact(j1 + j2 - j3) / dfact(j1 + j2 + j3 + 1));
    pref *= sqrt(dfact(j3 + m3) * dfact(j3 - m3) * dfact(j1 - m1) * dfact(j1 + m1) *
                 dfact(j2 - m2) * dfact(j2 + m2));
    double s = 0.0;
    for (int k = 0; k <= j1 + j2 - j3; k++) {
        int d0 = k, d1 = j1 + j2 - j3 - k, d2 = j1 - m1 - k;
        int d3 = j2 + m2 - k, d4 = j3 - j2 + m1 + k, d5 = j3 - j1 - m2 + k;
        if (d0 < 0 || d1 < 0 || d2 < 0 || d3 < 0 || d4 < 0 || d5 < 0) continue;
        double den = dfact(d0) * dfact(d1) * dfact(d2) * dfact(d3) * dfact(d4) * dfact(d5);
        s += ((k & 1) ? -1.0 : 1.0) / den;
    }
    return pref * s;
}

__device__ void u_real_entry(int l, int a, int i, double& re, double& im) {
    re = 0.0; im = 0.0;
    const double r2inv = 0.7071067811865475244;
    if (a == l) { if (i == l) re = 1.0; return; }
    if (a > l) {
        int m = a - l;
        if (i == l + m)      re = ((m & 1) ? -1.0 : 1.0) * r2inv;
        else if (i == l - m) re = r2inv;
    } else {
        int m = l - a;
        if (i == l - m)      im = r2inv;
        else if (i == l + m) im = -((m & 1) ? -1.0 : 1.0) * r2inv;
    }
}

__global__ void cg_kernel() {
    int p = blockIdx.x;
    int l1 = c_pl1[p], l2 = c_pl2[p], l3 = c_pl3[p];
    int d1 = 2 * l1 + 1, d2 = 2 * l2 + 1, d3 = 2 * l3 + 1;
    int ne = d1 * d2 * d3;
    __shared__ double Rr[125], Ri[125];
    __shared__ double s_inv;
    __shared__ int s_useR;
    int t = threadIdx.x;

    for (int e = t; e < 125; e += blockDim.x) g_cg[p * 125 + e] = 0.0f;

    for (int e = t; e < ne; e += blockDim.x) {
        int a = e / (d2 * d3);
        int rem = e - a * d2 * d3;
        int b = rem / d3;
        int c = rem - b * d3;
        double sr = 0.0, si = 0.0;
        for (int i = 0; i < d1; i++) {
            for (int j = 0; j < d2; j++) {
                int m1 = i - l1, m2 = j - l2, m3 = m1 + m2;
                if (m3 < -l3 || m3 > l3) continue;
                int kk = m3 + l3;
                double cc = clebsch_d(l1, m1, l2, m2, l3, m3);
                if (cc == 0.0) continue;
                double u1r, u1i, u2r, u2i, u3r, u3i;
                u_real_entry(l1, a, i, u1r, u1i);
                u_real_entry(l2, b, j, u2r, u2i);
                u_real_entry(l3, c, kk, u3r, u3i);
                u3i = -u3i;
                double pr = u1r * u2r - u1i * u2i;
                double pq = u1r * u2i + u1i * u2r;
                double qr = pr * u3r - pq * u3i;
                double qi = pr * u3i + pq * u3r;
                sr += qr * cc;
                si += qi * cc;
            }
        }
        Rr[e] = sr; Ri[e] = si;
    }
    __syncthreads();
    if (t == 0) {
        double a2 = 0.0, b2 = 0.0;
        for (int e = 0; e < ne; e++) { a2 += Rr[e] * Rr[e]; b2 += Ri[e] * Ri[e]; }
        int useR = sqrt(a2) >= sqrt(b2);
        s_useR = useR;
        s_inv = 1.0 / sqrt(useR ? a2 : b2);
    }
    __syncthreads();
    for (int e = t; e < ne; e += blockDim.x) {
        int a = e / (d2 * d3);
        int rem = e - a * d2 * d3;
        int b = rem / d3;
        int c = rem - b * d3;
        double val = (s_useR ? Rr[e] : Ri[e]) * s_inv;
        g_cg[p * 125 + (a * 5 + b) * 5 + c] = (float)val;
    }
}

// ---------------- node pre: up, skip ----------------
__global__ void node_pre(const float* __restrict__ node_feats,
                         const float* __restrict__ W_up,
                         const float* __restrict__ W_skip,
                         const int* __restrict__ specie) {
    const int NT = 160;
    int n = blockIdx.x;
    int t = threadIdx.x;
    __shared__ __align__(16) float sh_nf[FEAT];
    __shared__ __align__(16) float sh_up[FEAT];
    __shared__ __align__(16) float sh_sk[FEAT];

    const float4* row4 = (const float4*)(node_feats + (size_t)n * FEAT);
    for (int i = t; i < 144; i += NT) ((float4*)sh_nf)[i] = row4[i];
    __syncthreads();
    int sp = specie[n];
    for (int item = t; item < 144; item += NT) {
        int l, i, vg, off, d;
        decode_item(item, l, i, vg, off, d);
        const float4* Wu4 = (const float4*)(W_up + l * 4096) + vg;
        const float4* Ws4 = (const float4*)(W_skip + ((size_t)sp * 3 + l) * 4096) + vg;
        float4 au = make_float4(0.f,0.f,0.f,0.f);
        float4 as_ = make_float4(0.f,0.f,0.f,0.f);
        const float* nfp = sh_nf + off + i;
        #pragma unroll 8
        for (int u = 0; u < 64; u++) {
            float f = nfp[u * d];
            float4 wu = Wu4[u * 16];
            float4 ws = Ws4[u * 16];
            au.x += f * wu.x; au.y += f * wu.y; au.z += f * wu.z; au.w += f * wu.w;
            as_.x += f * ws.x; as_.y += f * ws.y; as_.z += f * ws.z; as_.w += f * ws.w;
        }
        int v0 = vg * 4;
        sh_up[off + (v0+0)*d + i] = au.x * 0.125f;
        sh_up[off + (v0+1)*d + i] = au.y * 0.125f;
        sh_up[off + (v0+2)*d + i] = au.z * 0.125f;
        sh_up[off + (v0+3)*d + i] = au.w * 0.125f;
        sh_sk[off + (v0+0)*d + i] = as_.x * 0.125f;
        sh_sk[off + (v0+1)*d + i] = as_.y * 0.125f;
        sh_sk[off + (v0+2)*d + i] = as_.z * 0.125f;
        sh_sk[off + (v0+3)*d + i] = as_.w * 0.125f;
    }
    __syncthreads();
    float4* up4 = (float4*)(g_up + (size_t)n * FEAT);
    float4* sk4 = (float4*)(g_skip + (size_t)n * FEAT);
    for (int i = t; i < 144; i += NT) {
        up4[i] = ((float4*)sh_up)[i];
        sk4[i] = ((float4*)sh_sk)[i];
    }
}

// ---------------- edge basis ----------------
__global__ void edge_basis(const float* __restrict__ vectors,
                           const float* __restrict__ M1,
                           const float* __restrict__ M2) {
    int E0 = blockIdx.x * 32;
    int t = threadIdx.x;
    __shared__ float s_len[32], s_coef[32];
    __shared__ float s_r[32][8];
    __shared__ float s_h1[32][64];

    if (t < 32) {
        int e = E0 + t;
        float vx = vectors[3*e], vy = vectors[3*e+1], vz = vectors[3*e+2];
        float len = sqrtf(vx*vx + vy*vy + vz*vz);
        float safe = (len == 0.0f) ? 1.0f : len;
        float env = 0.0f;
        if (len < 1.0f) {
            float dnm = fminf(len*len - 1.0f, -1e-6f);
            env = expf(2.0f * len * len / dnm);
        }
        s_len[t] = len;
        s_coef[t] = 1.4142135623730951f * env / safe;
    }
    __syncthreads();
    {
        int e = t >> 3, nb = t & 7;
        s_r[e][nb] = s_coef[e] * sinf(3.14159265358979323846f * (float)(nb+1) * s_len[e]);
    }
    __syncthreads();
    for (int idx = t; idx < 2048; idx += 256) {
        int e = idx >> 6, o = idx & 63;
        float acc = 0.0f;
        #pragma unroll
        for (int nb = 0; nb < 8; nb++) acc += s_r[e][nb] * M1[nb*64 + o];
        s_h1[e][o] = gelu_t(acc * 0.3535533905932738f);
    }
    __syncthreads();
    for (int idx = t; idx < 2048; idx += 256) {
        int e = idx >> 6, o = idx & 63;
        float acc = 0.0f;
        #pragma unroll 8
        for (int k = 0; k < 64; k++) acc += s_h1[e][k] * M2[k*64 + o];
        float h2 = gelu_t(acc * 0.125f);
        if (s_len[e] == 0.0f) h2 = 0.0f;
        g_h2[(size_t)(E0 + e) * 64 + o] = h2;
    }
}

// ---------------- w GEMM (TF32), o-chunk loop inside ----------------
__global__ void w_gemm_tf32() {
    int e0 = blockIdx.x * 64;
    int t = threadIdx.x;
    int wi = t >> 5;
    int lane = t & 31;
    int g = lane >> 2;
    int c = lane & 3;

    __shared__ __align__(16) uint32_t s_a[64][68];
    __shared__ __align__(16) uint32_t s_b[64][72];

    #pragma unroll
    for (int it = 0; it < 8; it++) {
        int idx = t + it * 128;
        int e = idx >> 4, k4 = idx & 15;
        float4 v = ((const float4*)(g_h2 + (size_t)(e0 + e) * 64))[k4];
        uint32_t* dst = &s_a[e][k4 * 4];
        dst[0] = f2tf32(v.x); dst[1] = f2tf32(v.y);
        dst[2] = f2tf32(v.z); dst[3] = f2tf32(v.w);
    }

    int eb = wi * 16;
    for (int oc = 0; oc < 11; oc++) {
        int o0 = oc * 64;
        if (oc > 0) __syncthreads();
        #pragma unroll
        for (int it = 0; it < 8; it++) {
            int idx = t + it * 128;
            int k = idx >> 4, o4 = idx & 15;
            uint4 v = ((const uint4*)(g_m3t + (size_t)k * 704 + o0))[o4];
            *(uint4*)&s_b[k][o4 * 4] = v;
        }
        __syncthreads();

        float acc[8][4];
        #pragma unroll
        for (int nt = 0; nt < 8; nt++)
            #pragma unroll
            for (int q = 0; q < 4; q++) acc[nt][q] = 0.0f;

        #pragma unroll
        for (int ks = 0; ks < 8; ks++) {
            int kb = ks * 8;
            uint32_t a0 = s_a[eb + g][kb + c];
            uint32_t a1 = s_a[eb + g + 8][kb + c];
            uint32_t a2 = s_a[eb + g][kb + c + 4];
            uint32_t a3 = s_a[eb + g + 8][kb + c + 4];
            #pragma unroll
            for (int nt = 0; nt < 8; nt++) {
                uint32_t b0 = s_b[kb + c][nt * 8 + g];
                uint32_t b1 = s_b[kb + c + 4][nt * 8 + g];
                asm volatile(
                    "mma.sync.aligned.m16n8k8.row.col.f32.tf32.tf32.f32 "
                    "{%0,%1,%2,%3}, {%4,%5,%6,%7}, {%8,%9}, {%0,%1,%2,%3};"
                    : "+f"(acc[nt][0]), "+f"(acc[nt][1]), "+f"(acc[nt][2]), "+f"(acc[nt][3])
                    : "r"(a0), "r"(a1), "r"(a2), "r"(a3), "r"(b0), "r"(b1));
            }
        }

        int er0 = e0 + eb + g;
        int er1 = er0 + 8;
        #pragma unroll
        for (int nt = 0; nt < 8; nt++) {
            int col = o0 + nt * 8 + 2 * c;
            float2 v0 = make_float2(acc[nt][0] * 0.125f, acc[nt][1] * 0.125f);
            float2 v1 = make_float2(acc[nt][2] * 0.125f, acc[nt][3] * 0.125f);
            *(float2*)(g_w + (size_t)er0 * 704 + col) = v0;
            *(float2*)(g_w + (size_t)er1 * 704 + col) = v1;
        }
    }
}

// ---------------- edge TP (R12 version) ----------------
__global__ void edge_tp(const float* __restrict__ vectors,
                        const int* __restrict__ senders) {
    const int EPB = 8;
    int E0 = blockIdx.x * EPB;
    int t = threadIdx.x;
    __shared__ __align__(16) float s_cg[1375];
    __shared__ __align__(16) float s_msg[EPB][576];
    __shared__ __align__(16) float s_Z[EPB][116];
    __shared__ float s_Y[EPB][9];
    __shared__ int s_send[EPB];

    if (t < EPB) {
        int e = E0 + t;
        s_send[t] = senders[e];
        float vx = vectors[3*e], vy = vectors[3*e+1], vz = vectors[3*e+2];
        float len = sqrtf(vx*vx + vy*vy + vz*vz);
        float il = 1.0f / fmaxf(len, 1e-9f);
        float dx = vx*il, dy = vy*il, dz = vz*il;
        const float SQ3 = 1.7320508075688772f;
        const float SQ15 = 3.872983346207417f;
        s_Y[t][0] = 1.0f;
        s_Y[t][1] = SQ3 * dy; s_Y[t][2] = SQ3 * dz; s_Y[t][3] = SQ3 * dx;
        s_Y[t][4] = SQ15 * dx * dy;
        s_Y[t][5] = SQ15 * dy * dz;
        s_Y[t][6] = 1.118033988749895f * (3.0f * dz * dz - 1.0f);
        s_Y[t][7] = SQ15 * dx * dz;
        s_Y[t][8] = 1.9364916731037085f * (dx * dx - dy * dy);
    }
    for (int i = t; i < 1375; i += 256) s_cg[i] = g_cg[i];
    __syncthreads();

    for (int idx = t; idx < EPB * 144; idx += 256) {
        int e = idx / 144, q = idx - 144 * e;
        ((float4*)s_msg[e])[q] = ((const float4*)(g_up + (size_t)s_send[e] * FEAT))[q];
    }
    __syncthreads();

    for (int idx = t; idx < EPB * 115; idx += 256) {
        int e = idx / 115, r = idx - 115 * e;
        int p = 0;
        while (r >= c_zoff[p + 1]) p++;
        int rr = r - c_zoff[p];
        int lf = c_pl2[p], lo = c_pl3[p];
        int dO = 2*lo + 1, dj = 2*lf + 1;
        int i = rr / dO, k = rr - dO * i;
        int yo = (lf == 0) ? 0 : ((lf == 1) ? 1 : 4);
        const float* cgp = s_cg + p*125 + i*25 + k;
        float acc = 0.0f;
        for (int j = 0; j < dj; j++) acc += s_Y[e][yo + j] * cgp[j*5];
        s_Z[e][r] = acc;
    }
    __syncthreads();

    float o0[2], o1[2][3], o2[2][5];
    #pragma unroll
    for (int it = 0; it < 2; it++) {
        int idx = t + it * 256;
        int e = idx >> 6, v = idx & 63;
        const float* M = s_msg[e];
        const float* Z = s_Z[e];
        const float* Wg = g_w + (size_t)(E0 + e) * 704 + v;

        float m0 = M[v];
        float m1a = M[64 + v*3], m1b = M[64 + v*3 + 1], m1c = M[64 + v*3 + 2];
        float m2a = M[256 + v*5], m2b = M[256 + v*5 + 1], m2c = M[256 + v*5 + 2];
        float m2d = M[256 + v*5 + 3], m2e = M[256 + v*5 + 4];

        float w0  = Wg[0*64], w1 = Wg[1*64], w2 = Wg[2*64], w3 = Wg[3*64];
        float w4  = Wg[4*64], w5 = Wg[5*64], w6 = Wg[6*64], w7 = Wg[7*64];
        float w8  = Wg[8*64], w9 = Wg[9*64], w10 = Wg[10*64];

        {
            float in0 = m0 * Z[0];
            float in4 = m1a*Z[18] + m1b*Z[19] + m1c*Z[20];
            float in9 = m2a*Z[85] + m2b*Z[86] + m2c*Z[87] + m2d*Z[88] + m2e*Z[89];
            o0[it] = w0*in0 + w4*in4 + w9*in9;
        }
        #pragma unroll
        for (int k = 0; k < 3; k++) {
            float in1 = m0 * Z[1 + k];
            float in3 = m1a*Z[9+k]  + m1b*Z[12+k] + m1c*Z[15+k];
            float in6 = m1a*Z[36+k] + m1b*Z[39+k] + m1c*Z[42+k];
            float in8 = m2a*Z[70+k] + m2b*Z[73+k] + m2c*Z[76+k]
                      + m2d*Z[79+k] + m2e*Z[82+k];
            o1[it][k] = w1*in1 + w3*in3 + w6*in6 + w8*in8;
        }
        #pragma unroll
        for (int k = 0; k < 5; k++) {
            float in2  = m0 * Z[4 + k];
            float in5  = m1a*Z[21+k] + m1b*Z[26+k] + m1c*Z[31+k];
            float in7  = m2a*Z[45+k] + m2b*Z[50+k] + m2c*Z[55+k]
                       + m2d*Z[60+k] + m2e*Z[65+k];
            float in10 = m2a*Z[90+k] + m2b*Z[95+k] + m2c*Z[100+k]
                       + m2d*Z[105+k] + m2e*Z[110+k];
            o2[it][k] = w2*in2 + w5*in5 + w7*in7 + w10*in10;
        }
    }
    __syncthreads();

    #pragma unroll
    for (int it = 0; it < 2; it++) {
        int idx = t + it * 256;
        int e = idx >> 6, v = idx & 63;
        float* row = g_w + (size_t)(E0 + e) * 704;
        row[v] = o0[it];
        #pragma unroll
        for (int k = 0; k < 3; k++) row[64 + v*3 + k] = o1[it][k];
        #pragma unroll
        for (int k = 0; k < 5; k++) row[256 + v*5 + k] = o2[it][k];
    }
}

// ---------------- node mid: CSR gather, dn, squares, write cats ----------------
#define NPB 2
__global__ void node_mid(const float* __restrict__ W_down) {
    const int NT = 160;
    int n0 = blockIdx.x * NPB;
    int t = threadIdx.x;
    __shared__ __align__(16) float sh_agg[NPB][FEAT];
    __shared__ __align__(16) float sh_dn[NPB][FEAT];
    __shared__ __align__(16) float sh_cat0[NPB][256];
    __shared__ __align__(16) float sh_cat1[NPB][576];
    __shared__ __align__(16) float sh_cat2[NPB][1280];
    __shared__ __align__(16) float s_cg[1375];

    // gather
    for (int i = t; i < 144 * NPB; i += NT) {
        int nn = i / 144, q = i - 144 * nn;
        int n = n0 + nn;
        int beg = g_off[n], end = g_off[n + 1];
        float4 a = make_float4(0.f, 0.f, 0.f, 0.f);
        for (int d = beg; d < end; d++) {
            int eid = g_elist[d];
            float4 v = ((const float4*)(g_w + (size_t)eid * 704))[q];
            a.x += v.x; a.y += v.y; a.z += v.z; a.w += v.w;
        }
        ((float4*)sh_agg[nn])[q] = a;
    }
    for (int i = t; i < 1375; i += NT) s_cg[i] = g_cg[i];
    __syncthreads();

    // dn
    const float dn_scale = 0.125f * 0.3535533905932738f;
    for (int item = t; item < 144; item += NT) {
        int l, i, vg, off, d;
        decode_item(item, l, i, vg, off, d);
        const float4* W4 = (const float4*)(W_down + l * 4096) + vg;
        float4 acc[NPB];
        #pragma unroll
        for (int nn = 0; nn < NPB; nn++) acc[nn] = make_float4(0.f,0.f,0.f,0.f);
        #pragma unroll 4
        for (int u = 0; u < 64; u++) {
            float4 w = W4[u * 16];
            #pragma unroll
            for (int nn = 0; nn < NPB; nn++) {
                float f = sh_agg[nn][off + u * d + i];
                acc[nn].x += f*w.x; acc[nn].y += f*w.y;
                acc[nn].z += f*w.z; acc[nn].w += f*w.w;
            }
        }
        int v0 = vg * 4;
        #pragma unroll
        for (int nn = 0; nn < NPB; nn++) {
            float4 a = acc[nn];
            a.x *= dn_scale; a.y *= dn_scale; a.z *= dn_scale; a.w *= dn_scale;
            if (l == 0) { a.x = gelu_t(a.x); a.y = gelu_t(a.y); a.z = gelu_t(a.z); a.w = gelu_t(a.w); }
            sh_dn[nn][off + (v0+0)*d + i] = a.x;
            sh_dn[nn][off + (v0+1)*d + i] = a.y;
            sh_dn[nn][off + (v0+2)*d + i] = a.z;
            sh_dn[nn][off + (v0+3)*d + i] = a.w;
        }
    }
    __syncthreads();

    // cat dn parts
    for (int i = t; i < 64 * NPB; i += NT)  { int nn = i >> 6, r = i & 63; sh_cat0[nn][r] = sh_dn[nn][r]; }
    for (int i = t; i < 192 * NPB; i += NT) { int nn = i / 192, r = i - 192*nn; sh_cat1[nn][r] = sh_dn[nn][64 + r]; }
    for (int i = t; i < 320 * NPB; i += NT) { int nn = i / 320, r = i - 320*nn; sh_cat2[nn][r] = sh_dn[nn][256 + r]; }

    // squares
    {
        const int sq_cg[8]  = {0, 4, 9, 1, 6, 2, 5, 10};
        const int sq_lA[8]  = {0, 1, 2, 0, 1, 0, 1, 2};
        const int sq_lB[8]  = {0, 1, 2, 1, 2, 2, 1, 2};
        const int sq_lO[8]  = {0, 0, 0, 1, 1, 2, 2, 2};
        const int sq_blk[8] = {1, 2, 3, 1, 2, 1, 2, 3};
        const int loff[3] = {0, 64, 256};
        #pragma unroll
        for (int sp = 0; sp < 8; sp++) {
            int lA = sq_lA[sp], lB = sq_lB[sp], lO = sq_lO[sp];
            int dA = 2*lA+1, dB = 2*lB+1, dO = 2*lO+1;
            int offA = loff[lA], offB = loff[lB];
            const float* cgp = s_cg + sq_cg[sp] * 125;
            int nout = 64 * dO;
            int blk = sq_blk[sp];
            for (int idx = t; idx < nout; idx += NT) {
                int u = idx / dO, k = idx - dO * u;
                float accs[NPB] = {0.f, 0.f};
                #pragma unroll
                for (int i = 0; i < dA; i++) {
                    #pragma unroll
                    for (int j = 0; j < dB; j++) {
                        float cgv = cgp[(i*5 + j)*5 + k];
                        #pragma unroll
                        for (int nn = 0; nn < NPB; nn++)
                            accs[nn] += sh_dn[nn][offA + u*dA + i]
                                      * sh_dn[nn][offB + u*dB + j] * cgv;
                    }
                }
                #pragma unroll
                for (int nn = 0; nn < NPB; nn++) {
                    if (lO == 0)      sh_cat0[nn][blk*64 + u] = accs[nn];
                    else if (lO == 1) sh_cat1[nn][(blk*64 + u)*3 + k] = accs[nn];
                    else              sh_cat2[nn][(blk*64 + u)*5 + k] = accs[nn];
                }
            }
        }
    }
    __syncthreads();

    // write cats in GEMM-row layout
    for (int idx = t; idx < NPB * 256; idx += NT) {
        int nn = idx >> 8, u = idx & 255;
        g_cat0[(size_t)(n0 + nn) * 256 + u] = sh_cat0[nn][u];
    }
    for (int idx = t; idx < NPB * 576; idx += NT) {
        int nn = idx / 576, r = idx - 576 * nn;
        int i = r / 192, u = r - 192 * i;
        g_cat1[((size_t)(n0 + nn) * 3 + i) * 192 + u] = sh_cat1[nn][u*3 + i];
    }
    for (int idx = t; idx < NPB * 1280; idx += NT) {
        int nn = idx / 1280, r = idx - 1280 * nn;
        int i = r / 256, u = r - 256 * i;
        g_cat2[((size_t)(n0 + nn) * 5 + i) * 256 + u] = sh_cat2[nn][u*5 + i];
    }
}

// ---------------- W_out GEMM (TF32): o[row, v] = scale * cat[row,:] @ W[:,v] ----------------
// l: 0/1/2 selects cat buffer, weight offset, K, scale, output mapping.
__global__ void wout_gemm_tf32(int l, int rows, int K, int woff, float scale) {
    int r0 = blockIdx.x * 64;
    int t = threadIdx.x;
    int wi = t >> 5;
    int lane = t & 31;
    int g = lane >> 2;
    int c = lane & 3;

    const float* cat = (l == 0) ? g_cat0 : ((l == 1) ? g_cat1 : g_cat2);

    __shared__ __align__(16) uint32_t s_a[64][68];
    __shared__ __align__(16) uint32_t s_b[64][72];

    float acc[8][4];
    #pragma unroll
    for (int nt = 0; nt < 8; nt++)
        #pragma unroll
        for (int q = 0; q < 4; q++) acc[nt][q] = 0.0f;

    int eb = wi * 16;
    int nchunks = K >> 6;
    for (int kc = 0; kc < nchunks; kc++) {
        if (kc > 0) __syncthreads();
        // fill A chunk: 64 rows x 64 k
        #pragma unroll
        for (int it = 0; it < 8; it++) {
            int idx = t + it * 128;
            int r = idx >> 4, k4 = idx & 15;
            int row = r0 + r;
            uint32_t* dst = &s_a[r][k4 * 4];
            if (row < rows) {
                float4 v = ((const float4*)(cat + (size_t)row * K + kc * 64))[k4];
                dst[0] = f2tf32(v.x); dst[1] = f2tf32(v.y);
                dst[2] = f2tf32(v.z); dst[3] = f2tf32(v.w);
            } else {
                dst[0] = 0; dst[1] = 0; dst[2] = 0; dst[3] = 0;
            }
        }
        // fill B chunk: 64 k x 64 v (already tf32)
        #pragma unroll
        for (int it = 0; it < 8; it++) {
            int idx = t + it * 128;
            int k = idx >> 4, o4 = idx & 15;
            uint4 v = ((const uint4*)(g_wt + (size_t)woff + (size_t)(kc * 64 + k) * 64))[o4];
            *(uint4*)&s_b[k][o4 * 4] = v;
        }
        __syncthreads();

        #pragma unroll
        for (int ks = 0; ks < 8; ks++) {
            int kb = ks * 8;
            uint32_t a0 = s_a[eb + g][kb + c];
            uint32_t a1 = s_a[eb + g + 8][kb + c];
            uint32_t a2 = s_a[eb + g][kb + c + 4];
            uint32_t a3 = s_a[eb + g + 8][kb + c + 4];
            #pragma unroll
            for (int nt = 0; nt < 8; nt++) {
                uint32_t b0 = s_b[kb + c][nt * 8 + g];
                uint32_t b1 = s_b[kb + c + 4][nt * 8 + g];
                asm volatile(
                    "mma.sync.aligned.m16n8k8.row.col.f32.tf32.tf32.f32 "
                    "{%0,%1,%2,%3}, {%4,%5,%6,%7}, {%8,%9}, {%0,%1,%2,%3};"
                    : "+f"(acc[nt][0]), "+f"(acc[nt][1]), "+f"(acc[nt][2]), "+f"(acc[nt][3])
                    : "r"(a0), "r"(a1), "r"(a2), "r"(a3), "r"(b0), "r"(b1));
            }
        }
    }

    // store into g_o with per-l mapping
    int er0 = r0 + eb + g;
    int er1 = er0 + 8;
    #pragma unroll
    for (int nt = 0; nt < 8; nt++) {
        int col = nt * 8 + 2 * c;
        #pragma unroll
        for (int h = 0; h < 2; h++) {
            int row = (h == 0) ? er0 : er1;
            if (row >= rows) continue;
            float va = acc[nt][h * 2 + 0] * scale;
            float vb = acc[nt][h * 2 + 1] * scale;
            size_t addr;
            if (l == 0) {
                addr = (size_t)row * FEAT + col;
                g_o[addr] = va; g_o[addr + 1] = vb;
            } else if (l == 1) {
                int n = row / 3, i = row - 3 * n;
                addr = (size_t)n * FEAT + 64 + (size_t)col * 3 + i;
                g_o[addr] = va; g_o[addr + 3] = vb;
            } else {
                int n = row / 5, i = row - 5 * n;
                addr = (size_t)n * FEAT + 256 + (size_t)col * 5 + i;
                g_o[addr] = va; g_o[addr + 5] = vb;
            }
        }
    }
}

// ---------------- node fin: softnorm + skip combine ----------------
__global__ void node_fin(float* __restrict__ out, int n_nodes) {
    int idx = blockIdx.x * 256 + threadIdx.x;   // one (n, l, v) group per thread
    int total = n_nodes * 192;
    if (idx >= total) return;
    int n = idx / 192, gq = idx - 192 * n;
    int l = gq >> 6, v = gq & 63;
    int off = (l == 0) ? 0 : ((l == 1) ? 64 : 256);
    int d = 2 * l + 1;
    size_t base = (size_t)n * FEAT + off + (size_t)v * d;
    float vals[5];
    float s2 = 0.0f;
    for (int j = 0; j < d; j++) { vals[j] = g_o[base + j]; s2 += vals[j] * vals[j]; }
    float nrm = sqrtf(s2) * 1e-5f;
    float sus = (nrm > 0.0f) ? expf(-1.0f / nrm) : 0.0f;
    float inv = 1.0f / (1.0f + nrm * sus);
    for (int j = 0; j < d; j++) {
        out[base + j] = 0.9f * g_skip[base + j] + 0.45f * vals[j] * inv;
    }
}

// ---------------- launch ----------------
extern "C" void kernel_launch(void* const* d_in, const int* in_sizes, int n_in,
                              void* d_out, int out_size) {
    const float* vectors    = (const float*)d_in[0];
    const float* node_feats = (const float*)d_in[1];
    const float* W_up       = (const float*)d_in[2];
    const float* W_skip     = (const float*)d_in[3];
    const float* M1         = (const float*)d_in[4];
    const float* M2         = (const float*)d_in[5];
    const float* M3         = (const float*)d_in[6];
    const float* W_out0     = (const float*)d_in[7];
    const float* W_out1     = (const float*)d_in[8];
    const float* W_out2     = (const float*)d_in[9];
    const float* W_down     = (const float*)d_in[10];
    const int*   specie     = (const int*)d_in[11];
    const int*   senders    = (const int*)d_in[12];
    const int*   receivers  = (const int*)d_in[13];

    int n_nodes = in_sizes[11];
    int n_edges = in_sizes[12];

    cg_kernel<<<11, 128>>>();
    m3_convert<<<(64 * 704 + 255) / 256, 256>>>(M3);
    wout_convert<<<(45056 + 255) / 256, 256>>>(W_out0, W_out1, W_out2);
    hist_zero<<<(n_nodes + 255) / 256, 256>>>();
    hist<<<(n_edges + 255) / 256, 256>>>(receivers, n_edges);
    scan_kernel<<<1, 1024>>>();
    scatter_ids<<<(n_edges + 255) / 256, 256>>>(receivers, n_edges);
    node_pre<<<n_nodes, 160>>>(node_feats, W_up, W_skip, specie);
    edge_basis<<<n_edges / 32, 256>>>(vectors, M1, M2);
    w_gemm_tf32<<<n_edges / 64, 128>>>();
    edge_tp<<<n_edges / 8, 256>>>(vectors, senders);
    node_mid<<<n_nodes / NPB, 160>>>(W_down);
    {
        int r0 = n_nodes;              // l=0 rows
        int r1 = n_nodes * 3;          // l=1 rows
        int r2 = n_nodes * 5;          // l=2 rows
        wout_gemm_tf32<<<(r0 + 63) / 64, 128>>>(0, r0, 256, 0,     0.0625f);
        wout_gemm_tf32<<<(r1 + 63) / 64, 128>>>(1, r1, 192, 16384, 0.07216878364870323f);
        wout_gemm_tf32<<<(r2 + 63) / 64, 128>>>(2, r2, 256, 28672, 0.0625f);
    }
    node_fin<<<(n_nodes * 192 + 255) / 256, 256>>>((float*)d_out, n_nodes);
}

// round 16
// speedup vs baseline: 1.3876x; 1.0640x over previous
#include <cuda_runtime.h>
#include <cuda_fp16.h>
#include <math.h>
#include <stdint.h>

#define N_NODES 20000
#define N_EDGES 160000
#define FEAT 576   // 64*1 + 64*3 + 64*5

// ---------------- scratch (device globals, no allocation) ----------------
__device__ __align__(16) float g_cg[11 * 125];
__device__ __align__(16) float g_up[N_NODES * FEAT];
__device__ __align__(16) float g_skip[N_NODES * FEAT];
__device__ __align__(16) float g_h2[(size_t)N_EDGES * 64];
__device__ __align__(16) __half g_wh[(size_t)N_EDGES * 704];   // w coefficients, fp16
__device__ __align__(16) float g_w[(size_t)N_EDGES * 576];     // TP outputs, fp32
__device__ __align__(16) uint32_t g_m3t[64 * 704];             // M3 tf32
__device__ __align__(16) uint32_t g_wt[45056];                 // W_out0|1|2 tf32
__device__ __align__(16) float g_cat0[(size_t)N_NODES * 256];
__device__ __align__(16) float g_cat1[(size_t)N_NODES * 3 * 192];
__device__ __align__(16) float g_cat2[(size_t)N_NODES * 5 * 256];
__device__ __align__(16) float g_o[(size_t)N_NODES * FEAT];
__device__ int g_cnt[N_NODES];
__device__ int g_cur[N_NODES];
__device__ int g_off[N_NODES + 1];
__device__ int g_elist[N_EDGES];

__constant__ int c_pl1[11] = {0,0,0,1,1,1,1,2,2,2,2};
__constant__ int c_pl2[11] = {0,1,2,0,1,1,2,0,1,2,2};
__constant__ int c_pl3[11] = {0,1,2,1,0,2,1,2,1,0,2};
__constant__ int c_zoff[12] = {0,1,4,9,18,21,36,45,70,85,90,115};

// ---------------- helpers ----------------
__device__ __forceinline__ float gelu_t(float x) {
    float x3 = x * x * x;
    return 0.5f * x * (1.0f + tanhf(0.7978845608028654f * (x + 0.044715f * x3)));
}

__device__ __forceinline__ void decode_item(int item, int& l, int& i, int& vg,
                                            int& off, int& d) {
    if (item < 16)      { l = 0; i = 0; vg = item; off = 0; d = 1; }
    else if (item < 64) { int r = item - 16; l = 1; i = r >> 4; vg = r & 15; off = 64;  d = 3; }
    else                { int r = item - 64; l = 2; i = r >> 4; vg = r & 15; off = 256; d = 5; }
}

__device__ __forceinline__ uint32_t f2tf32(float x) {
    uint32_t r;
    asm("cvt.rna.tf32.f32 %0, %1;" : "=r"(r) : "f"(x));
    return r;
}

// ---------------- weight tf32 pre-conversion ----------------
__global__ void m3_convert(const float* __restrict__ M3) {
    int i = blockIdx.x * 256 + threadIdx.x;
    if (i < 64 * 704) g_m3t[i] = f2tf32(M3[i]);
}
__global__ void wout_convert(const float* __restrict__ W0,
                             const float* __restrict__ W1,
                             const float* __restrict__ W2) {
    int i = blockIdx.x * 256 + threadIdx.x;
    if (i < 16384)       g_wt[i] = f2tf32(W0[i]);
    else if (i < 28672)  g_wt[i] = f2tf32(W1[i - 16384]);
    else if (i < 45056)  g_wt[i] = f2tf32(W2[i - 28672]);
}

// ---------------- CSR build ----------------
__global__ void hist_zero() {
    int i = blockIdx.x * 256 + threadIdx.x;
    if (i < N_NODES) { g_cnt[i] = 0; g_cur[i] = 0; }
}
__global__ void hist(const int* __restrict__ recv, int n_edges) {
    int e = blockIdx.x * 256 + threadIdx.x;
    if (e < n_edges) atomicAdd(&g_cnt[recv[e]], 1);
}
__global__ void scan_kernel() {
    __shared__ int warp_sums[32];
    int t = threadIdx.x;
    int lane = t & 31, wid = t >> 5;
    int base = t * 20;
    int s = 0;
    #pragma unroll 4
    for (int i = 0; i < 20; i++) { int idx = base + i; if (idx < N_NODES) s += g_cnt[idx]; }
    int v = s;
    #pragma unroll
    for (int o = 1; o < 32; o <<= 1) {
        int u = __shfl_up_sync(0xFFFFFFFF, v, o);
        if (lane >= o) v += u;
    }
    if (lane == 31) warp_sums[wid] = v;
    __syncthreads();
    if (wid == 0) {
        int w = warp_sums[lane];
        #pragma unroll
        for (int o = 1; o < 32; o <<= 1) {
            int u = __shfl_up_sync(0xFFFFFFFF, w, o);
            if (lane >= o) w += u;
        }
        warp_sums[lane] = w;
    }
    __syncthreads();
    int run = (wid > 0 ? warp_sums[wid - 1] : 0) + v - s;
    for (int i = 0; i < 20; i++) {
        int idx = base + i;
        if (idx < N_NODES) { g_off[idx] = run; run += g_cnt[idx]; }
    }
    if (t == 1023) g_off[N_NODES] = run;
}
__global__ void scatter_ids(const int* __restrict__ recv, int n_edges) {
    int e = blockIdx.x * 256 + threadIdx.x;
    if (e < n_edges) {
        int r = recv[e];
        int p = atomicAdd(&g_cur[r], 1);
        g_elist[g_off[r] + p] = e;
    }
}

// ---------------- CG computation (exact port of reference) ----------------
__device__ double dfact(int n) {
    double r = 1.0;
    for (int i = 2; i <= n; i++) r *= (double)i;
    return r;
}

__device__ double clebsch_d(int j1, int m1, int j2, int m2, int j3, int m3) {
    if (m1 + m2 != m3) return 0.0;
    double pref = sqrt((2.0 * j3 + 1.0) * dfact(j3 + j1 - j2) * dfact(j3 - j1 + j2) *
                       dfact(j1 + j2 - j3) / dfact(j1 + j2 + j3 + 1));
    pref *= sqrt(dfact(j3 + m3) * dfact(j3 - m3) * dfact(j1 - m1) * dfact(j1 + m1) *
                 dfact(j2 - m2) * dfact(j2 + m2));
    double s = 0.0;
    for (int k = 0; k <= j1 + j2 - j3; k++) {
        int d0 = k, d1 = j1 + j2 - j3 - k, d2 = j1 - m1 - k;
        int d3 = j2 + m2 - k, d4 = j3 - j2 + m1 + k, d5 = j3 - j1 - m2 + k;
        if (d0 < 0 || d1 < 0 || d2 < 0 || d3 < 0 || d4 < 0 || d5 < 0) continue;
        double den = dfact(d0) * dfact(d1) * dfact(d2) * dfact(d3) * dfact(d4) * dfact(d5);
        s += ((k & 1) ? -1.0 : 1.0) / den;
    }
    return pref * s;
}

__device__ void u_real_entry(int l, int a, int i, double& re, double& im) {
    re = 0.0; im = 0.0;
    const double r2inv = 0.7071067811865475244;
    if (a == l) { if (i == l) re = 1.0; return; }
    if (a > l) {
        int m = a - l;
        if (i == l + m)      re = ((m & 1) ? -1.0 : 1.0) * r2inv;
        else if (i == l - m) re = r2inv;
    } else {
        int m = l - a;
        if (i == l - m)      im = r2inv;
        else if (i == l + m) im = -((m & 1) ? -1.0 : 1.0) * r2inv;
    }
}

__global__ void cg_kernel() {
    int p = blockIdx.x;
    int l1 = c_pl1[p], l2 = c_pl2[p], l3 = c_pl3[p];
    int d1 = 2 * l1 + 1, d2 = 2 * l2 + 1, d3 = 2 * l3 + 1;
    int ne = d1 * d2 * d3;
    __shared__ double Rr[125], Ri[125];
    __shared__ double s_inv;
    __shared__ int s_useR;
    int t = threadIdx.x;

    for (int e = t; e < 125; e += blockDim.x) g_cg[p * 125 + e] = 0.0f;

    for (int e = t; e < ne; e += blockDim.x) {
        int a = e / (d2 * d3);
        int rem = e - a * d2 * d3;
        int b = rem / d3;
        int c = rem - b * d3;
        double sr = 0.0, si = 0.0;
        for (int i = 0; i < d1; i++) {
            for (int j = 0; j < d2; j++) {
                int m1 = i - l1, m2 = j - l2, m3 = m1 + m2;
                if (m3 < -l3 || m3 > l3) continue;
                int kk = m3 + l3;
                double cc = clebsch_d(l1, m1, l2, m2, l3, m3);
                if (cc == 0.0) continue;
                double u1r, u1i, u2r, u2i, u3r, u3i;
                u_real_entry(l1, a, i, u1r, u1i);
                u_real_entry(l2, b, j, u2r, u2i);
                u_real_entry(l3, c, kk, u3r, u3i);
                u3i = -u3i;
                double pr = u1r * u2r - u1i * u2i;
                double pq = u1r * u2i + u1i * u2r;
                double qr = pr * u3r - pq * u3i;
                double qi = pr * u3i + pq * u3r;
                sr += qr * cc;
                si += qi * cc;
            }
        }
        Rr[e] = sr; Ri[e] = si;
    }
    __syncthreads();
    if (t == 0) {
        double a2 = 0.0, b2 = 0.0;
        for (int e = 0; e < ne; e++) { a2 += Rr[e] * Rr[e]; b2 += Ri[e] * Ri[e]; }
        int useR = sqrt(a2) >= sqrt(b2);
        s_useR = useR;
        s_inv = 1.0 / sqrt(useR ? a2 : b2);
    }
    __syncthreads();
    for (int e = t; e < ne; e += blockDim.x) {
        int a = e / (d2 * d3);
        int rem = e - a * d2 * d3;
        int b = rem / d3;
        int c = rem - b * d3;
        double val = (s_useR ? Rr[e] : Ri[e]) * s_inv;
        g_cg[p * 125 + (a * 5 + b) * 5 + c] = (float)val;
    }
}

// ---------------- node pre: up, skip ----------------
__global__ void node_pre(const float* __restrict__ node_feats,
                         const float* __restrict__ W_up,
                         const float* __restrict__ W_skip,
                         const int* __restrict__ specie) {
    const int NT = 160;
    int n = blockIdx.x;
    int t = threadIdx.x;
    __shared__ __align__(16) float sh_nf[FEAT];
    __shared__ __align__(16) float sh_up[FEAT];
    __shared__ __align__(16) float sh_sk[FEAT];

    const float4* row4 = (const float4*)(node_feats + (size_t)n * FEAT);
    for (int i = t; i < 144; i += NT) ((float4*)sh_nf)[i] = row4[i];
    __syncthreads();
    int sp = specie[n];
    for (int item = t; item < 144; item += NT) {
        int l, i, vg, off, d;
        decode_item(item, l, i, vg, off, d);
        const float4* Wu4 = (const float4*)(W_up + l * 4096) + vg;
        const float4* Ws4 = (const float4*)(W_skip + ((size_t)sp * 3 + l) * 4096) + vg;
        float4 au = make_float4(0.f,0.f,0.f,0.f);
        float4 as_ = make_float4(0.f,0.f,0.f,0.f);
        const float* nfp = sh_nf + off + i;
        #pragma unroll 8
        for (int u = 0; u < 64; u++) {
            float f = nfp[u * d];
            float4 wu = Wu4[u * 16];
            float4 ws = Ws4[u * 16];
            au.x += f * wu.x; au.y += f * wu.y; au.z += f * wu.z; au.w += f * wu.w;
            as_.x += f * ws.x; as_.y += f * ws.y; as_.z += f * ws.z; as_.w += f * ws.w;
        }
        int v0 = vg * 4;
        sh_up[off + (v0+0)*d + i] = au.x * 0.125f;
        sh_up[off + (v0+1)*d + i] = au.y * 0.125f;
        sh_up[off + (v0+2)*d + i] = au.z * 0.125f;
        sh_up[off + (v0+3)*d + i] = au.w * 0.125f;
        sh_sk[off + (v0+0)*d + i] = as_.x * 0.125f;
        sh_sk[off + (v0+1)*d + i] = as_.y * 0.125f;
        sh_sk[off + (v0+2)*d + i] = as_.z * 0.125f;
        sh_sk[off + (v0+3)*d + i] = as_.w * 0.125f;
    }
    __syncthreads();
    float4* up4 = (float4*)(g_up + (size_t)n * FEAT);
    float4* sk4 = (float4*)(g_skip + (size_t)n * FEAT);
    for (int i = t; i < 144; i += NT) {
        up4[i] = ((float4*)sh_up)[i];
        sk4[i] = ((float4*)sh_sk)[i];
    }
}

// ---------------- edge basis ----------------
__global__ void edge_basis(const float* __restrict__ vectors,
                           const float* __restrict__ M1,
                           const float* __restrict__ M2) {
    int E0 = blockIdx.x * 32;
    int t = threadIdx.x;
    __shared__ float s_len[32], s_coef[32];
    __shared__ float s_r[32][8];
    __shared__ float s_h1[32][64];

    if (t < 32) {
        int e = E0 + t;
        float vx = vectors[3*e], vy = vectors[3*e+1], vz = vectors[3*e+2];
        float len = sqrtf(vx*vx + vy*vy + vz*vz);
        float safe = (len == 0.0f) ? 1.0f : len;
        float env = 0.0f;
        if (len < 1.0f) {
            float dnm = fminf(len*len - 1.0f, -1e-6f);
            env = expf(2.0f * len * len / dnm);
        }
        s_len[t] = len;
        s_coef[t] = 1.4142135623730951f * env / safe;
    }
    __syncthreads();
    {
        int e = t >> 3, nb = t & 7;
        s_r[e][nb] = s_coef[e] * sinf(3.14159265358979323846f * (float)(nb+1) * s_len[e]);
    }
    __syncthreads();
    for (int idx = t; idx < 2048; idx += 256) {
        int e = idx >> 6, o = idx & 63;
        float acc = 0.0f;
        #pragma unroll
        for (int nb = 0; nb < 8; nb++) acc += s_r[e][nb] * M1[nb*64 + o];
        s_h1[e][o] = gelu_t(acc * 0.3535533905932738f);
    }
    __syncthreads();
    for (int idx = t; idx < 2048; idx += 256) {
        int e = idx >> 6, o = idx & 63;
        float acc = 0.0f;
        #pragma unroll 8
        for (int k = 0; k < 64; k++) acc += s_h1[e][k] * M2[k*64 + o];
        float h2 = gelu_t(acc * 0.125f);
        if (s_len[e] == 0.0f) h2 = 0.0f;
        g_h2[(size_t)(E0 + e) * 64 + o] = h2;
    }
}

// ---------------- w GEMM (TF32), o-chunk loop; fp16 output ----------------
__global__ void w_gemm_tf32() {
    int e0 = blockIdx.x * 64;
    int t = threadIdx.x;
    int wi = t >> 5;
    int lane = t & 31;
    int g = lane >> 2;
    int c = lane & 3;

    __shared__ __align__(16) uint32_t s_a[64][68];
    __shared__ __align__(16) uint32_t s_b[64][72];

    #pragma unroll
    for (int it = 0; it < 8; it++) {
        int idx = t + it * 128;
        int e = idx >> 4, k4 = idx & 15;
        float4 v = ((const float4*)(g_h2 + (size_t)(e0 + e) * 64))[k4];
        uint32_t* dst = &s_a[e][k4 * 4];
        dst[0] = f2tf32(v.x); dst[1] = f2tf32(v.y);
        dst[2] = f2tf32(v.z); dst[3] = f2tf32(v.w);
    }

    int eb = wi * 16;
    for (int oc = 0; oc < 11; oc++) {
        int o0 = oc * 64;
        if (oc > 0) __syncthreads();
        #pragma unroll
        for (int it = 0; it < 8; it++) {
            int idx = t + it * 128;
            int k = idx >> 4, o4 = idx & 15;
            uint4 v = ((const uint4*)(g_m3t + (size_t)k * 704 + o0))[o4];
            *(uint4*)&s_b[k][o4 * 4] = v;
        }
        __syncthreads();

        float acc[8][4];
        #pragma unroll
        for (int nt = 0; nt < 8; nt++)
            #pragma unroll
            for (int q = 0; q < 4; q++) acc[nt][q] = 0.0f;

        #pragma unroll
        for (int ks = 0; ks < 8; ks++) {
            int kb = ks * 8;
            uint32_t a0 = s_a[eb + g][kb + c];
            uint32_t a1 = s_a[eb + g + 8][kb + c];
            uint32_t a2 = s_a[eb + g][kb + c + 4];
            uint32_t a3 = s_a[eb + g + 8][kb + c + 4];
            #pragma unroll
            for (int nt = 0; nt < 8; nt++) {
                uint32_t b0 = s_b[kb + c][nt * 8 + g];
                uint32_t b1 = s_b[kb + c + 4][nt * 8 + g];
                asm volatile(
                    "mma.sync.aligned.m16n8k8.row.col.f32.tf32.tf32.f32 "
                    "{%0,%1,%2,%3}, {%4,%5,%6,%7}, {%8,%9}, {%0,%1,%2,%3};"
                    : "+f"(acc[nt][0]), "+f"(acc[nt][1]), "+f"(acc[nt][2]), "+f"(acc[nt][3])
                    : "r"(a0), "r"(a1), "r"(a2), "r"(a3), "r"(b0), "r"(b1));
            }
        }

        int er0 = e0 + eb + g;
        int er1 = er0 + 8;
        #pragma unroll
        for (int nt = 0; nt < 8; nt++) {
            int col = o0 + nt * 8 + 2 * c;
            __half2 h0 = __floats2half2_rn(acc[nt][0] * 0.125f, acc[nt][1] * 0.125f);
            __half2 h1 = __floats2half2_rn(acc[nt][2] * 0.125f, acc[nt][3] * 0.125f);
            *(__half2*)(g_wh + (size_t)er0 * 704 + col) = h0;
            *(__half2*)(g_wh + (size_t)er1 * 704 + col) = h1;
        }
    }
}

// ---------------- edge TP: w from fp16, TP output to g_w (dense 576) ----------------
__global__ void edge_tp(const float* __restrict__ vectors,
                        const int* __restrict__ senders) {
    const int EPB = 8;
    int E0 = blockIdx.x * EPB;
    int t = threadIdx.x;
    __shared__ __align__(16) float s_cg[1375];
    __shared__ __align__(16) float s_msg[EPB][576];
    __shared__ __align__(16) float s_Z[EPB][116];
    __shared__ float s_Y[EPB][9];
    __shared__ int s_send[EPB];

    if (t < EPB) {
        int e = E0 + t;
        s_send[t] = senders[e];
        float vx = vectors[3*e], vy = vectors[3*e+1], vz = vectors[3*e+2];
        float len = sqrtf(vx*vx + vy*vy + vz*vz);
        float il = 1.0f / fmaxf(len, 1e-9f);
        float dx = vx*il, dy = vy*il, dz = vz*il;
        const float SQ3 = 1.7320508075688772f;
        const float SQ15 = 3.872983346207417f;
        s_Y[t][0] = 1.0f;
        s_Y[t][1] = SQ3 * dy; s_Y[t][2] = SQ3 * dz; s_Y[t][3] = SQ3 * dx;
        s_Y[t][4] = SQ15 * dx * dy;
        s_Y[t][5] = SQ15 * dy * dz;
        s_Y[t][6] = 1.118033988749895f * (3.0f * dz * dz - 1.0f);
        s_Y[t][7] = SQ15 * dx * dz;
        s_Y[t][8] = 1.9364916731037085f * (dx * dx - dy * dy);
    }
    for (int i = t; i < 1375; i += 256) s_cg[i] = g_cg[i];
    __syncthreads();

    for (int idx = t; idx < EPB * 144; idx += 256) {
        int e = idx / 144, q = idx - 144 * e;
        ((float4*)s_msg[e])[q] = ((const float4*)(g_up + (size_t)s_send[e] * FEAT))[q];
    }
    __syncthreads();

    for (int idx = t; idx < EPB * 115; idx += 256) {
        int e = idx / 115, r = idx - 115 * e;
        int p = 0;
        while (r >= c_zoff[p + 1]) p++;
        int rr = r - c_zoff[p];
        int lf = c_pl2[p], lo = c_pl3[p];
        int dO = 2*lo + 1, dj = 2*lf + 1;
        int i = rr / dO, k = rr - dO * i;
        int yo = (lf == 0) ? 0 : ((lf == 1) ? 1 : 4);
        const float* cgp = s_cg + p*125 + i*25 + k;
        float acc = 0.0f;
        for (int j = 0; j < dj; j++) acc += s_Y[e][yo + j] * cgp[j*5];
        s_Z[e][r] = acc;
    }
    __syncthreads();

    // TP: 2 items per thread; w from g_wh (fp16); output direct to g_w (no hazard)
    #pragma unroll
    for (int it = 0; it < 2; it++) {
        int idx = t + it * 256;
        int e = idx >> 6, v = idx & 63;
        const float* M = s_msg[e];
        const float* Z = s_Z[e];
        const __half* Wg = g_wh + (size_t)(E0 + e) * 704 + v;

        float m0 = M[v];
        float m1a = M[64 + v*3], m1b = M[64 + v*3 + 1], m1c = M[64 + v*3 + 2];
        float m2a = M[256 + v*5], m2b = M[256 + v*5 + 1], m2c = M[256 + v*5 + 2];
        float m2d = M[256 + v*5 + 3], m2e = M[256 + v*5 + 4];

        float w0  = __half2float(Wg[0*64]),  w1 = __half2float(Wg[1*64]);
        float w2  = __half2float(Wg[2*64]),  w3 = __half2float(Wg[3*64]);
        float w4  = __half2float(Wg[4*64]),  w5 = __half2float(Wg[5*64]);
        float w6  = __half2float(Wg[6*64]),  w7 = __half2float(Wg[7*64]);
        float w8  = __half2float(Wg[8*64]),  w9 = __half2float(Wg[9*64]);
        float w10 = __half2float(Wg[10*64]);

        float* row = g_w + (size_t)(E0 + e) * 576;

        // lo=0
        {
            float in0 = m0 * Z[0];
            float in4 = m1a*Z[18] + m1b*Z[19] + m1c*Z[20];
            float in9 = m2a*Z[85] + m2b*Z[86] + m2c*Z[87] + m2d*Z[88] + m2e*Z[89];
            row[v] = w0*in0 + w4*in4 + w9*in9;
        }
        // lo=1, k=0..2
        #pragma unroll
        for (int k = 0; k < 3; k++) {
            float in1 = m0 * Z[1 + k];
            float in3 = m1a*Z[9+k]  + m1b*Z[12+k] + m1c*Z[15+k];
            float in6 = m1a*Z[36+k] + m1b*Z[39+k] + m1c*Z[42+k];
            float in8 = m2a*Z[70+k] + m2b*Z[73+k] + m2c*Z[76+k]
                      + m2d*Z[79+k] + m2e*Z[82+k];
            row[64 + v*3 + k] = w1*in1 + w3*in3 + w6*in6 + w8*in8;
        }
        // lo=2, k=0..4
        #pragma unroll
        for (int k = 0; k < 5; k++) {
            float in2  = m0 * Z[4 + k];
            float in5  = m1a*Z[21+k] + m1b*Z[26+k] + m1c*Z[31+k];
            float in7  = m2a*Z[45+k] + m2b*Z[50+k] + m2c*Z[55+k]
                       + m2d*Z[60+k] + m2e*Z[65+k];
            float in10 = m2a*Z[90+k] + m2b*Z[95+k] + m2c*Z[100+k]
                       + m2d*Z[105+k] + m2e*Z[110+k];
            row[256 + v*5 + k] = w2*in2 + w5*in5 + w7*in7 + w10*in10;
        }
    }
}

// ---------------- node mid: CSR gather, dn, squares, write cats ----------------
#define NPB 2
__global__ void node_mid(const float* __restrict__ W_down) {
    const int NT = 160;
    int n0 = blockIdx.x * NPB;
    int t = threadIdx.x;
    __shared__ __align__(16) float sh_agg[NPB][FEAT];
    __shared__ __align__(16) float sh_dn[NPB][FEAT];
    __shared__ __align__(16) float sh_cat0[NPB][256];
    __shared__ __align__(16) float sh_cat1[NPB][576];
    __shared__ __align__(16) float sh_cat2[NPB][1280];
    __shared__ __align__(16) float s_cg[1375];

    // gather
    for (int i = t; i < 144 * NPB; i += NT) {
        int nn = i / 144, q = i - 144 * nn;
        int n = n0 + nn;
        int beg = g_off[n], end = g_off[n + 1];
        float4 a = make_float4(0.f, 0.f, 0.f, 0.f);
        for (int d = beg; d < end; d++) {
            int eid = g_elist[d];
            float4 v = ((const float4*)(g_w + (size_t)eid * 576))[q];
            a.x += v.x; a.y += v.y; a.z += v.z; a.w += v.w;
        }
        ((float4*)sh_agg[nn])[q] = a;
    }
    for (int i = t; i < 1375; i += NT) s_cg[i] = g_cg[i];
    __syncthreads();

    // dn
    const float dn_scale = 0.125f * 0.3535533905932738f;
    for (int item = t; item < 144; item += NT) {
        int l, i, vg, off, d;
        decode_item(item, l, i, vg, off, d);
        const float4* W4 = (const float4*)(W_down + l * 4096) + vg;
        float4 acc[NPB];
        #pragma unroll
        for (int nn = 0; nn < NPB; nn++) acc[nn] = make_float4(0.f,0.f,0.f,0.f);
        #pragma unroll 4
        for (int u = 0; u < 64; u++) {
            float4 w = W4[u * 16];
            #pragma unroll
            for (int nn = 0; nn < NPB; nn++) {
                float f = sh_agg[nn][off + u * d + i];
                acc[nn].x += f*w.x; acc[nn].y += f*w.y;
                acc[nn].z += f*w.z; acc[nn].w += f*w.w;
            }
        }
        int v0 = vg * 4;
        #pragma unroll
        for (int nn = 0; nn < NPB; nn++) {
            float4 a = acc[nn];
            a.x *= dn_scale; a.y *= dn_scale; a.z *= dn_scale; a.w *= dn_scale;
            if (l == 0) { a.x = gelu_t(a.x); a.y = gelu_t(a.y); a.z = gelu_t(a.z); a.w = gelu_t(a.w); }
            sh_dn[nn][off + (v0+0)*d + i] = a.x;
            sh_dn[nn][off + (v0+1)*d + i] = a.y;
            sh_dn[nn][off + (v0+2)*d + i] = a.z;
            sh_dn[nn][off + (v0+3)*d + i] = a.w;
        }
    }
    __syncthreads();

    // cat dn parts
    for (int i = t; i < 64 * NPB; i += NT)  { int nn = i >> 6, r = i & 63; sh_cat0[nn][r] = sh_dn[nn][r]; }
    for (int i = t; i < 192 * NPB; i += NT) { int nn = i / 192, r = i - 192*nn; sh_cat1[nn][r] = sh_dn[nn][64 + r]; }
    for (int i = t; i < 320 * NPB; i += NT) { int nn = i / 320, r = i - 320*nn; sh_cat2[nn][r] = sh_dn[nn][256 + r]; }

    // squares
    {
        const int sq_cg[8]  = {0, 4, 9, 1, 6, 2, 5, 10};
        const int sq_lA[8]  = {0, 1, 2, 0, 1, 0, 1, 2};
        const int sq_lB[8]  = {0, 1, 2, 1, 2, 2, 1, 2};
        const int sq_lO[8]  = {0, 0, 0, 1, 1, 2, 2, 2};
        const int sq_blk[8] = {1, 2, 3, 1, 2, 1, 2, 3};
        const int loff[3] = {0, 64, 256};
        #pragma unroll
        for (int sp = 0; sp < 8; sp++) {
            int lA = sq_lA[sp], lB = sq_lB[sp], lO = sq_lO[sp];
            int dA = 2*lA+1, dB = 2*lB+1, dO = 2*lO+1;
            int offA = loff[lA], offB = loff[lB];
            const float* cgp = s_cg + sq_cg[sp] * 125;
            int nout = 64 * dO;
            int blk = sq_blk[sp];
            for (int idx = t; idx < nout; idx += NT) {
                int u = idx / dO, k = idx - dO * u;
                float accs[NPB] = {0.f, 0.f};
                #pragma unroll
                for (int i = 0; i < dA; i++) {
                    #pragma unroll
                    for (int j = 0; j < dB; j++) {
                        float cgv = cgp[(i*5 + j)*5 + k];
                        #pragma unroll
                        for (int nn = 0; nn < NPB; nn++)
                            accs[nn] += sh_dn[nn][offA + u*dA + i]
                                      * sh_dn[nn][offB + u*dB + j] * cgv;
                    }
                }
                #pragma unroll
                for (int nn = 0; nn < NPB; nn++) {
                    if (lO == 0)      sh_cat0[nn][blk*64 + u] = accs[nn];
                    else if (lO == 1) sh_cat1[nn][(blk*64 + u)*3 + k] = accs[nn];
                    else              sh_cat2[nn][(blk*64 + u)*5 + k] = accs[nn];
                }
            }
        }
    }
    __syncthreads();

    // write cats in GEMM-row layout
    for (int idx = t; idx < NPB * 256; idx += NT) {
        int nn = idx >> 8, u = idx & 255;
        g_cat0[(size_t)(n0 + nn) * 256 + u] = sh_cat0[nn][u];
    }
    for (int idx = t; idx < NPB * 576; idx += NT) {
        int nn = idx / 576, r = idx - 576 * nn;
        int i = r / 192, u = r - 192 * i;
        g_cat1[((size_t)(n0 + nn) * 3 + i) * 192 + u] = sh_cat1[nn][u*3 + i];
    }
    for (int idx = t; idx < NPB * 1280; idx += NT) {
        int nn = idx / 1280, r = idx - 1280 * nn;
        int i = r / 256, u = r - 256 * i;
        g_cat2[((size_t)(n0 + nn) * 5 + i) * 256 + u] = sh_cat2[nn][u*5 + i];
    }
}

// ---------------- W_out GEMM (TF32) ----------------
__global__ void wout_gemm_tf32(int l, int rows, int K, int woff, float scale) {
    int r0 = blockIdx.x * 64;
    int t = threadIdx.x;
    int wi = t >> 5;
    int lane = t & 31;
    int g = lane >> 2;
    int c = lane & 3;

    const float* cat = (l == 0) ? g_cat0 : ((l == 1) ? g_cat1 : g_cat2);

    __shared__ __align__(16) uint32_t s_a[64][68];
    __shared__ __align__(16) uint32_t s_b[64][72];

    float acc[8][4];
    #pragma unroll
    for (int nt = 0; nt < 8; nt++)
        #pragma unroll
        for (int q = 0; q < 4; q++) acc[nt][q] = 0.0f;

    int eb = wi * 16;
    int nchunks = K >> 6;
    for (int kc = 0; kc < nchunks; kc++) {
        if (kc > 0) __syncthreads();
        #pragma unroll
        for (int it = 0; it < 8; it++) {
            int idx = t + it * 128;
            int r = idx >> 4, k4 = idx & 15;
            int row = r0 + r;
            uint32_t* dst = &s_a[r][k4 * 4];
            if (row < rows) {
                float4 v = ((const float4*)(cat + (size_t)row * K + kc * 64))[k4];
                dst[0] = f2tf32(v.x); dst[1] = f2tf32(v.y);
                dst[2] = f2tf32(v.z); dst[3] = f2tf32(v.w);
            } else {
                dst[0] = 0; dst[1] = 0; dst[2] = 0; dst[3] = 0;
            }
        }
        #pragma unroll
        for (int it = 0; it < 8; it++) {
            int idx = t + it * 128;
            int k = idx >> 4, o4 = idx & 15;
            uint4 v = ((const uint4*)(g_wt + (size_t)woff + (size_t)(kc * 64 + k) * 64))[o4];
            *(uint4*)&s_b[k][o4 * 4] = v;
        }
        __syncthreads();

        #pragma unroll
        for (int ks = 0; ks < 8; ks++) {
            int kb = ks * 8;
            uint32_t a0 = s_a[eb + g][kb + c];
            uint32_t a1 = s_a[eb + g + 8][kb + c];
            uint32_t a2 = s_a[eb + g][kb + c + 4];
            uint32_t a3 = s_a[eb + g + 8][kb + c + 4];
            #pragma unroll
            for (int nt = 0; nt < 8; nt++) {
                uint32_t b0 = s_b[kb + c][nt * 8 + g];
                uint32_t b1 = s_b[kb + c + 4][nt * 8 + g];
                asm volatile(
                    "mma.sync.aligned.m16n8k8.row.col.f32.tf32.tf32.f32 "
                    "{%0,%1,%2,%3}, {%4,%5,%6,%7}, {%8,%9}, {%0,%1,%2,%3};"
                    : "+f"(acc[nt][0]), "+f"(acc[nt][1]), "+f"(acc[nt][2]), "+f"(acc[nt][3])
                    : "r"(a0), "r"(a1), "r"(a2), "r"(a3), "r"(b0), "r"(b1));
            }
        }
    }

    int er0 = r0 + eb + g;
    int er1 = er0 + 8;
    #pragma unroll
    for (int nt = 0; nt < 8; nt++) {
        int col = nt * 8 + 2 * c;
        #pragma unroll
        for (int h = 0; h < 2; h++) {
            int row = (h == 0) ? er0 : er1;
            if (row >= rows) continue;
            float va = acc[nt][h * 2 + 0] * scale;
            float vb = acc[nt][h * 2 + 1] * scale;
            size_t addr;
            if (l == 0) {
                addr = (size_t)row * FEAT + col;
                g_o[addr] = va; g_o[addr + 1] = vb;
            } else if (l == 1) {
                int n = row / 3, i = row - 3 * n;
                addr = (size_t)n * FEAT + 64 + (size_t)col * 3 + i;
                g_o[addr] = va; g_o[addr + 3] = vb;
            } else {
                int n = row / 5, i = row - 5 * n;
                addr = (size_t)n * FEAT + 256 + (size_t)col * 5 + i;
                g_o[addr] = va; g_o[addr + 5] = vb;
            }
        }
    }
}

// ---------------- node fin: softnorm + skip combine ----------------
__global__ void node_fin(float* __restrict__ out, int n_nodes) {
    int idx = blockIdx.x * 256 + threadIdx.x;
    int total = n_nodes * 192;
    if (idx >= total) return;
    int n = idx / 192, gq = idx - 192 * n;
    int l = gq >> 6, v = gq & 63;
    int off = (l == 0) ? 0 : ((l == 1) ? 64 : 256);
    int d = 2 * l + 1;
    size_t base = (size_t)n * FEAT + off + (size_t)v * d;
    float vals[5];
    float s2 = 0.0f;
    for (int j = 0; j < d; j++) { vals[j] = g_o[base + j]; s2 += vals[j] * vals[j]; }
    float nrm = sqrtf(s2) * 1e-5f;
    float sus = (nrm > 0.0f) ? expf(-1.0f / nrm) : 0.0f;
    float inv = 1.0f / (1.0f + nrm * sus);
    for (int j = 0; j < d; j++) {
        out[base + j] = 0.9f * g_skip[base + j] + 0.45f * vals[j] * inv;
    }
}

// ---------------- launch ----------------
extern "C" void kernel_launch(void* const* d_in, const int* in_sizes, int n_in,
                              void* d_out, int out_size) {
    const float* vectors    = (const float*)d_in[0];
    const float* node_feats = (const float*)d_in[1];
    const float* W_up       = (const float*)d_in[2];
    const float* W_skip     = (const float*)d_in[3];
    const float* M1         = (const float*)d_in[4];
    const float* M2         = (const float*)d_in[5];
    const float* M3         = (const float*)d_in[6];
    const float* W_out0     = (const float*)d_in[7];
    const float* W_out1     = (const float*)d_in[8];
    const float* W_out2     = (const float*)d_in[9];
    const float* W_down     = (const float*)d_in[10];
    const int*   specie     = (const int*)d_in[11];
    const int*   senders    = (const int*)d_in[12];
    const int*   receivers  = (const int*)d_in[13];

    int n_nodes = in_sizes[11];
    int n_edges = in_sizes[12];

    cg_kernel<<<11, 128>>>();
    m3_convert<<<(64 * 704 + 255) / 256, 256>>>(M3);
    wout_convert<<<(45056 + 255) / 256, 256>>>(W_out0, W_out1, W_out2);
    hist_zero<<<(n_nodes + 255) / 256, 256>>>();
    hist<<<(n_edges + 255) / 256, 256>>>(receivers, n_edges);
    scan_kernel<<<1, 1024>>>();
    scatter_ids<<<(n_edges + 255) / 256, 256>>>(receivers, n_edges);
    node_pre<<<n_nodes, 160>>>(node_feats, W_up, W_skip, specie);
    edge_basis<<<n_edges / 32, 256>>>(vectors, M1, M2);
    w_gemm_tf32<<<n_edges / 64, 128>>>();
    edge_tp<<<n_edges / 8, 256>>>(vectors, senders);
    node_mid<<<n_nodes / NPB, 160>>>(W_down);
    {
        int r0 = n_nodes;
        int r1 = n_nodes * 3;
        int r2 = n_nodes * 5;
        wout_gemm_tf32<<<(r0 + 63) / 64, 128>>>(0, r0, 256, 0,     0.0625f);
        wout_gemm_tf32<<<(r1 + 63) / 64, 128>>>(1, r1, 192, 16384, 0.07216878364870323f);
        wout_gemm_tf32<<<(r2 + 63) / 64, 128>>>(2, r2, 256, 28672, 0.0625f);
    }
    node_fin<<<(n_nodes * 192 + 255) / 256, 256>>>((float*)d_out, n_nodes);
}

// round 17
// speedup vs baseline: 1.3985x; 1.0079x over previous
#include <cuda_runtime.h>
#include <cuda_fp16.h>
#include <math.h>
#include <stdint.h>

#define N_NODES 20000
#define N_EDGES 160000
#define FEAT 576   // 64*1 + 64*3 + 64*5

// ---------------- scratch (device globals, no allocation) ----------------
__device__ __align__(16) float g_cg[11 * 125];
__device__ __align__(16) float g_up[N_NODES * FEAT];
__device__ __align__(16) float g_skip[N_NODES * FEAT];
__device__ __align__(16) float g_h2[(size_t)N_EDGES * 64];
__device__ __align__(16) __half g_wh[(size_t)N_EDGES * 704];   // w coefficients, fp16
__device__ __align__(16) __half g_wo[(size_t)N_EDGES * 576];   // TP outputs, fp16
__device__ __align__(16) uint32_t g_m3t[64 * 704];             // M3 tf32
__device__ __align__(16) uint32_t g_wt[45056];                 // W_out0|1|2 tf32
__device__ __align__(16) float g_cat0[(size_t)N_NODES * 256];
__device__ __align__(16) float g_cat1[(size_t)N_NODES * 3 * 192];
__device__ __align__(16) float g_cat2[(size_t)N_NODES * 5 * 256];
__device__ __align__(16) float g_o[(size_t)N_NODES * FEAT];
__device__ int g_cnt[N_NODES];
__device__ int g_cur[N_NODES];
__device__ int g_off[N_NODES + 1];
__device__ int g_elist[N_EDGES];

__constant__ int c_pl1[11] = {0,0,0,1,1,1,1,2,2,2,2};
__constant__ int c_pl2[11] = {0,1,2,0,1,1,2,0,1,2,2};
__constant__ int c_pl3[11] = {0,1,2,1,0,2,1,2,1,0,2};
__constant__ int c_zoff[12] = {0,1,4,9,18,21,36,45,70,85,90,115};

// ---------------- helpers ----------------
__device__ __forceinline__ float gelu_t(float x) {
    float x3 = x * x * x;
    return 0.5f * x * (1.0f + tanhf(0.7978845608028654f * (x + 0.044715f * x3)));
}

__device__ __forceinline__ void decode_item(int item, int& l, int& i, int& vg,
                                            int& off, int& d) {
    if (item < 16)      { l = 0; i = 0; vg = item; off = 0; d = 1; }
    else if (item < 64) { int r = item - 16; l = 1; i = r >> 4; vg = r & 15; off = 64;  d = 3; }
    else                { int r = item - 64; l = 2; i = r >> 4; vg = r & 15; off = 256; d = 5; }
}

__device__ __forceinline__ uint32_t f2tf32(float x) {
    uint32_t r;
    asm("cvt.rna.tf32.f32 %0, %1;" : "=r"(r) : "f"(x));
    return r;
}

// ---------------- prep: weight tf32 conversions + CSR zero (one launch) ----------------
__global__ void prep(const float* __restrict__ M3,
                     const float* __restrict__ W0,
                     const float* __restrict__ W1,
                     const float* __restrict__ W2) {
    int i = blockIdx.x * 256 + threadIdx.x;
    if (i < 45056) g_m3t[i] = f2tf32(M3[i]);
    if (i < 16384)       g_wt[i] = f2tf32(W0[i]);
    else if (i < 28672)  g_wt[i] = f2tf32(W1[i - 16384]);
    else if (i < 45056)  g_wt[i] = f2tf32(W2[i - 28672]);
    if (i < N_NODES) { g_cnt[i] = 0; g_cur[i] = 0; }
}

// ---------------- CSR build ----------------
__global__ void hist(const int* __restrict__ recv, int n_edges) {
    int e = blockIdx.x * 256 + threadIdx.x;
    if (e < n_edges) atomicAdd(&g_cnt[recv[e]], 1);
}
__global__ void scan_kernel() {
    __shared__ int warp_sums[32];
    int t = threadIdx.x;
    int lane = t & 31, wid = t >> 5;
    int base = t * 20;
    int s = 0;
    #pragma unroll 4
    for (int i = 0; i < 20; i++) { int idx = base + i; if (idx < N_NODES) s += g_cnt[idx]; }
    int v = s;
    #pragma unroll
    for (int o = 1; o < 32; o <<= 1) {
        int u = __shfl_up_sync(0xFFFFFFFF, v, o);
        if (lane >= o) v += u;
    }
    if (lane == 31) warp_sums[wid] = v;
    __syncthreads();
    if (wid == 0) {
        int w = warp_sums[lane];
        #pragma unroll
        for (int o = 1; o < 32; o <<= 1) {
            int u = __shfl_up_sync(0xFFFFFFFF, w, o);
            if (lane >= o) w += u;
        }
        warp_sums[lane] = w;
    }
    __syncthreads();
    int run = (wid > 0 ? warp_sums[wid - 1] : 0) + v - s;
    for (int i = 0; i < 20; i++) {
        int idx = base + i;
        if (idx < N_NODES) { g_off[idx] = run; run += g_cnt[idx]; }
    }
    if (t == 1023) g_off[N_NODES] = run;
}
__global__ void scatter_ids(const int* __restrict__ recv, int n_edges) {
    int e = blockIdx.x * 256 + threadIdx.x;
    if (e < n_edges) {
        int r = recv[e];
        int p = atomicAdd(&g_cur[r], 1);
        g_elist[g_off[r] + p] = e;
    }
}

// ---------------- CG computation (exact port of reference) ----------------
__device__ double dfact(int n) {
    double r = 1.0;
    for (int i = 2; i <= n; i++) r *= (double)i;
    return r;
}

__device__ double clebsch_d(int j1, int m1, int j2, int m2, int j3, int m3) {
    if (m1 + m2 != m3) return 0.0;
    double pref = sqrt((2.0 * j3 + 1.0) * dfact(j3 + j1 - j2) * dfact(j3 - j1 + j2) *
                       dfact(j1 + j2 - j3) / dfact(j1 + j2 + j3 + 1));
    pref *= sqrt(dfact(j3 + m3) * dfact(j3 - m3) * dfact(j1 - m1) * dfact(j1 + m1) *
                 dfact(j2 - m2) * dfact(j2 + m2));
    double s = 0.0;
    for (int k = 0; k <= j1 + j2 - j3; k++) {
        int d0 = k, d1 = j1 + j2 - j3 - k, d2 = j1 - m1 - k;
        int d3 = j2 + m2 - k, d4 = j3 - j2 + m1 + k, d5 = j3 - j1 - m2 + k;
        if (d0 < 0 || d1 < 0 || d2 < 0 || d3 < 0 || d4 < 0 || d5 < 0) continue;
        double den = dfact(d0) * dfact(d1) * dfact(d2) * dfact(d3) * dfact(d4) * dfact(d5);
        s += ((k & 1) ? -1.0 : 1.0) / den;
    }
    return pref * s;
}

__device__ void u_real_entry(int l, int a, int i, double& re, double& im) {
    re = 0.0; im = 0.0;
    const double r2inv = 0.7071067811865475244;
    if (a == l) { if (i == l) re = 1.0; return; }
    if (a > l) {
        int m = a - l;
        if (i == l + m)      re = ((m & 1) ? -1.0 : 1.0) * r2inv;
        else if (i == l - m) re = r2inv;
    } else {
        int m = l - a;
        if (i == l - m)      im = r2inv;
        else if (i == l + m) im = -((m & 1) ? -1.0 : 1.0) * r2inv;
    }
}

__global__ void cg_kernel() {
    int p = blockIdx.x;
    int l1 = c_pl1[p], l2 = c_pl2[p], l3 = c_pl3[p];
    int d1 = 2 * l1 + 1, d2 = 2 * l2 + 1, d3 = 2 * l3 + 1;
    int ne = d1 * d2 * d3;
    __shared__ double Rr[125], Ri[125];
    __shared__ double s_inv;
    __shared__ int s_useR;
    int t = threadIdx.x;

    for (int e = t; e < 125; e += blockDim.x) g_cg[p * 125 + e] = 0.0f;

    for (int e = t; e < ne; e += blockDim.x) {
        int a = e / (d2 * d3);
        int rem = e - a * d2 * d3;
        int b = rem / d3;
        int c = rem - b * d3;
        double sr = 0.0, si = 0.0;
        for (int i = 0; i < d1; i++) {
            for (int j = 0; j < d2; j++) {
                int m1 = i - l1, m2 = j - l2, m3 = m1 + m2;
                if (m3 < -l3 || m3 > l3) continue;
                int kk = m3 + l3;
                double cc = clebsch_d(l1, m1, l2, m2, l3, m3);
                if (cc == 0.0) continue;
                double u1r, u1i, u2r, u2i, u3r, u3i;
                u_real_entry(l1, a, i, u1r, u1i);
                u_real_entry(l2, b, j, u2r, u2i);
                u_real_entry(l3, c, kk, u3r, u3i);
                u3i = -u3i;
                double pr = u1r * u2r - u1i * u2i;
                double pq = u1r * u2i + u1i * u2r;
                double qr = pr * u3r - pq * u3i;
                double qi = pr * u3i + pq * u3r;
                sr += qr * cc;
                si += qi * cc;
            }
        }
        Rr[e] = sr; Ri[e] = si;
    }
    __syncthreads();
    if (t == 0) {
        double a2 = 0.0, b2 = 0.0;
        for (int e = 0; e < ne; e++) { a2 += Rr[e] * Rr[e]; b2 += Ri[e] * Ri[e]; }
        int useR = sqrt(a2) >= sqrt(b2);
        s_useR = useR;
        s_inv = 1.0 / sqrt(useR ? a2 : b2);
    }
    __syncthreads();
    for (int e = t; e < ne; e += blockDim.x) {
        int a = e / (d2 * d3);
        int rem = e - a * d2 * d3;
        int b = rem / d3;
        int c = rem - b * d3;
        double val = (s_useR ? Rr[e] : Ri[e]) * s_inv;
        g_cg[p * 125 + (a * 5 + b) * 5 + c] = (float)val;
    }
}

// ---------------- node pre: up, skip ----------------
__global__ void node_pre(const float* __restrict__ node_feats,
                         const float* __restrict__ W_up,
                         const float* __restrict__ W_skip,
                         const int* __restrict__ specie) {
    const int NT = 160;
    int n = blockIdx.x;
    int t = threadIdx.x;
    __shared__ __align__(16) float sh_nf[FEAT];
    __shared__ __align__(16) float sh_up[FEAT];
    __shared__ __align__(16) float sh_sk[FEAT];

    const float4* row4 = (const float4*)(node_feats + (size_t)n * FEAT);
    for (int i = t; i < 144; i += NT) ((float4*)sh_nf)[i] = row4[i];
    __syncthreads();
    int sp = specie[n];
    for (int item = t; item < 144; item += NT) {
        int l, i, vg, off, d;
        decode_item(item, l, i, vg, off, d);
        const float4* Wu4 = (const float4*)(W_up + l * 4096) + vg;
        const float4* Ws4 = (const float4*)(W_skip + ((size_t)sp * 3 + l) * 4096) + vg;
        float4 au = make_float4(0.f,0.f,0.f,0.f);
        float4 as_ = make_float4(0.f,0.f,0.f,0.f);
        const float* nfp = sh_nf + off + i;
        #pragma unroll 8
        for (int u = 0; u < 64; u++) {
            float f = nfp[u * d];
            float4 wu = Wu4[u * 16];
            float4 ws = Ws4[u * 16];
            au.x += f * wu.x; au.y += f * wu.y; au.z += f * wu.z; au.w += f * wu.w;
            as_.x += f * ws.x; as_.y += f * ws.y; as_.z += f * ws.z; as_.w += f * ws.w;
        }
        int v0 = vg * 4;
        sh_up[off + (v0+0)*d + i] = au.x * 0.125f;
        sh_up[off + (v0+1)*d + i] = au.y * 0.125f;
        sh_up[off + (v0+2)*d + i] = au.z * 0.125f;
        sh_up[off + (v0+3)*d + i] = au.w * 0.125f;
        sh_sk[off + (v0+0)*d + i] = as_.x * 0.125f;
        sh_sk[off + (v0+1)*d + i] = as_.y * 0.125f;
        sh_sk[off + (v0+2)*d + i] = as_.z * 0.125f;
        sh_sk[off + (v0+3)*d + i] = as_.w * 0.125f;
    }
    __syncthreads();
    float4* up4 = (float4*)(g_up + (size_t)n * FEAT);
    float4* sk4 = (float4*)(g_skip + (size_t)n * FEAT);
    for (int i = t; i < 144; i += NT) {
        up4[i] = ((float4*)sh_up)[i];
        sk4[i] = ((float4*)sh_sk)[i];
    }
}

// ---------------- edge basis ----------------
__global__ void edge_basis(const float* __restrict__ vectors,
                           const float* __restrict__ M1,
                           const float* __restrict__ M2) {
    int E0 = blockIdx.x * 32;
    int t = threadIdx.x;
    __shared__ float s_len[32], s_coef[32];
    __shared__ float s_r[32][8];
    __shared__ float s_h1[32][64];

    if (t < 32) {
        int e = E0 + t;
        float vx = vectors[3*e], vy = vectors[3*e+1], vz = vectors[3*e+2];
        float len = sqrtf(vx*vx + vy*vy + vz*vz);
        float safe = (len == 0.0f) ? 1.0f : len;
        float env = 0.0f;
        if (len < 1.0f) {
            float dnm = fminf(len*len - 1.0f, -1e-6f);
            env = expf(2.0f * len * len / dnm);
        }
        s_len[t] = len;
        s_coef[t] = 1.4142135623730951f * env / safe;
    }
    __syncthreads();
    {
        int e = t >> 3, nb = t & 7;
        s_r[e][nb] = s_coef[e] * sinf(3.14159265358979323846f * (float)(nb+1) * s_len[e]);
    }
    __syncthreads();
    for (int idx = t; idx < 2048; idx += 256) {
        int e = idx >> 6, o = idx & 63;
        float acc = 0.0f;
        #pragma unroll
        for (int nb = 0; nb < 8; nb++) acc += s_r[e][nb] * M1[nb*64 + o];
        s_h1[e][o] = gelu_t(acc * 0.3535533905932738f);
    }
    __syncthreads();
    for (int idx = t; idx < 2048; idx += 256) {
        int e = idx >> 6, o = idx & 63;
        float acc = 0.0f;
        #pragma unroll 8
        for (int k = 0; k < 64; k++) acc += s_h1[e][k] * M2[k*64 + o];
        float h2 = gelu_t(acc * 0.125f);
        if (s_len[e] == 0.0f) h2 = 0.0f;
        g_h2[(size_t)(E0 + e) * 64 + o] = h2;
    }
}

// ---------------- w GEMM (TF32), o-chunk loop; fp16 output ----------------
__global__ void w_gemm_tf32() {
    int e0 = blockIdx.x * 64;
    int t = threadIdx.x;
    int wi = t >> 5;
    int lane = t & 31;
    int g = lane >> 2;
    int c = lane & 3;

    __shared__ __align__(16) uint32_t s_a[64][68];
    __shared__ __align__(16) uint32_t s_b[64][72];

    #pragma unroll
    for (int it = 0; it < 8; it++) {
        int idx = t + it * 128;
        int e = idx >> 4, k4 = idx & 15;
        float4 v = ((const float4*)(g_h2 + (size_t)(e0 + e) * 64))[k4];
        uint32_t* dst = &s_a[e][k4 * 4];
        dst[0] = f2tf32(v.x); dst[1] = f2tf32(v.y);
        dst[2] = f2tf32(v.z); dst[3] = f2tf32(v.w);
    }

    int eb = wi * 16;
    for (int oc = 0; oc < 11; oc++) {
        int o0 = oc * 64;
        if (oc > 0) __syncthreads();
        #pragma unroll
        for (int it = 0; it < 8; it++) {
            int idx = t + it * 128;
            int k = idx >> 4, o4 = idx & 15;
            uint4 v = ((const uint4*)(g_m3t + (size_t)k * 704 + o0))[o4];
            *(uint4*)&s_b[k][o4 * 4] = v;
        }
        __syncthreads();

        float acc[8][4];
        #pragma unroll
        for (int nt = 0; nt < 8; nt++)
            #pragma unroll
            for (int q = 0; q < 4; q++) acc[nt][q] = 0.0f;

        #pragma unroll
        for (int ks = 0; ks < 8; ks++) {
            int kb = ks * 8;
            uint32_t a0 = s_a[eb + g][kb + c];
            uint32_t a1 = s_a[eb + g + 8][kb + c];
            uint32_t a2 = s_a[eb + g][kb + c + 4];
            uint32_t a3 = s_a[eb + g + 8][kb + c + 4];
            #pragma unroll
            for (int nt = 0; nt < 8; nt++) {
                uint32_t b0 = s_b[kb + c][nt * 8 + g];
                uint32_t b1 = s_b[kb + c + 4][nt * 8 + g];
                asm volatile(
                    "mma.sync.aligned.m16n8k8.row.col.f32.tf32.tf32.f32 "
                    "{%0,%1,%2,%3}, {%4,%5,%6,%7}, {%8,%9}, {%0,%1,%2,%3};"
                    : "+f"(acc[nt][0]), "+f"(acc[nt][1]), "+f"(acc[nt][2]), "+f"(acc[nt][3])
                    : "r"(a0), "r"(a1), "r"(a2), "r"(a3), "r"(b0), "r"(b1));
            }
        }

        int er0 = e0 + eb + g;
        int er1 = er0 + 8;
        #pragma unroll
        for (int nt = 0; nt < 8; nt++) {
            int col = o0 + nt * 8 + 2 * c;
            __half2 h0 = __floats2half2_rn(acc[nt][0] * 0.125f, acc[nt][1] * 0.125f);
            __half2 h1 = __floats2half2_rn(acc[nt][2] * 0.125f, acc[nt][3] * 0.125f);
            *(__half2*)(g_wh + (size_t)er0 * 704 + col) = h0;
            *(__half2*)(g_wh + (size_t)er1 * 704 + col) = h1;
        }
    }
}

// ---------------- edge TP: w from fp16, TP output to g_wo (fp16, dense 576) ----------------
__global__ void edge_tp(const float* __restrict__ vectors,
                        const int* __restrict__ senders) {
    const int EPB = 8;
    int E0 = blockIdx.x * EPB;
    int t = threadIdx.x;
    __shared__ __align__(16) float s_cg[1375];
    __shared__ __align__(16) float s_msg[EPB][576];
    __shared__ __align__(16) float s_Z[EPB][116];
    __shared__ float s_Y[EPB][9];
    __shared__ int s_send[EPB];

    if (t < EPB) {
        int e = E0 + t;
        s_send[t] = senders[e];
        float vx = vectors[3*e], vy = vectors[3*e+1], vz = vectors[3*e+2];
        float len = sqrtf(vx*vx + vy*vy + vz*vz);
        float il = 1.0f / fmaxf(len, 1e-9f);
        float dx = vx*il, dy = vy*il, dz = vz*il;
        const float SQ3 = 1.7320508075688772f;
        const float SQ15 = 3.872983346207417f;
        s_Y[t][0] = 1.0f;
        s_Y[t][1] = SQ3 * dy; s_Y[t][2] = SQ3 * dz; s_Y[t][3] = SQ3 * dx;
        s_Y[t][4] = SQ15 * dx * dy;
        s_Y[t][5] = SQ15 * dy * dz;
        s_Y[t][6] = 1.118033988749895f * (3.0f * dz * dz - 1.0f);
        s_Y[t][7] = SQ15 * dx * dz;
        s_Y[t][8] = 1.9364916731037085f * (dx * dx - dy * dy);
    }
    for (int i = t; i < 1375; i += 256) s_cg[i] = g_cg[i];
    __syncthreads();

    for (int idx = t; idx < EPB * 144; idx += 256) {
        int e = idx / 144, q = idx - 144 * e;
        ((float4*)s_msg[e])[q] = ((const float4*)(g_up + (size_t)s_send[e] * FEAT))[q];
    }
    __syncthreads();

    for (int idx = t; idx < EPB * 115; idx += 256) {
        int e = idx / 115, r = idx - 115 * e;
        int p = 0;
        while (r >= c_zoff[p + 1]) p++;
        int rr = r - c_zoff[p];
        int lf = c_pl2[p], lo = c_pl3[p];
        int dO = 2*lo + 1, dj = 2*lf + 1;
        int i = rr / dO, k = rr - dO * i;
        int yo = (lf == 0) ? 0 : ((lf == 1) ? 1 : 4);
        const float* cgp = s_cg + p*125 + i*25 + k;
        float acc = 0.0f;
        for (int j = 0; j < dj; j++) acc += s_Y[e][yo + j] * cgp[j*5];
        s_Z[e][r] = acc;
    }
    __syncthreads();

    #pragma unroll
    for (int it = 0; it < 2; it++) {
        int idx = t + it * 256;
        int e = idx >> 6, v = idx & 63;
        const float* M = s_msg[e];
        const float* Z = s_Z[e];
        const __half* Wg = g_wh + (size_t)(E0 + e) * 704 + v;

        float m0 = M[v];
        float m1a = M[64 + v*3], m1b = M[64 + v*3 + 1], m1c = M[64 + v*3 + 2];
        float m2a = M[256 + v*5], m2b = M[256 + v*5 + 1], m2c = M[256 + v*5 + 2];
        float m2d = M[256 + v*5 + 3], m2e = M[256 + v*5 + 4];

        float w0  = __half2float(Wg[0*64]),  w1 = __half2float(Wg[1*64]);
        float w2  = __half2float(Wg[2*64]),  w3 = __half2float(Wg[3*64]);
        float w4  = __half2float(Wg[4*64]),  w5 = __half2float(Wg[5*64]);
        float w6  = __half2float(Wg[6*64]),  w7 = __half2float(Wg[7*64]);
        float w8  = __half2float(Wg[8*64]),  w9 = __half2float(Wg[9*64]);
        float w10 = __half2float(Wg[10*64]);

        __half* row = g_wo + (size_t)(E0 + e) * 576;

        // lo=0
        {
            float in0 = m0 * Z[0];
            float in4 = m1a*Z[18] + m1b*Z[19] + m1c*Z[20];
            float in9 = m2a*Z[85] + m2b*Z[86] + m2c*Z[87] + m2d*Z[88] + m2e*Z[89];
            row[v] = __float2half(w0*in0 + w4*in4 + w9*in9);
        }
        // lo=1, k=0..2
        #pragma unroll
        for (int k = 0; k < 3; k++) {
            float in1 = m0 * Z[1 + k];
            float in3 = m1a*Z[9+k]  + m1b*Z[12+k] + m1c*Z[15+k];
            float in6 = m1a*Z[36+k] + m1b*Z[39+k] + m1c*Z[42+k];
            float in8 = m2a*Z[70+k] + m2b*Z[73+k] + m2c*Z[76+k]
                      + m2d*Z[79+k] + m2e*Z[82+k];
            row[64 + v*3 + k] = __float2half(w1*in1 + w3*in3 + w6*in6 + w8*in8);
        }
        // lo=2, k=0..4
        #pragma unroll
        for (int k = 0; k < 5; k++) {
            float in2  = m0 * Z[4 + k];
            float in5  = m1a*Z[21+k] + m1b*Z[26+k] + m1c*Z[31+k];
            float in7  = m2a*Z[45+k] + m2b*Z[50+k] + m2c*Z[55+k]
                       + m2d*Z[60+k] + m2e*Z[65+k];
            float in10 = m2a*Z[90+k] + m2b*Z[95+k] + m2c*Z[100+k]
                       + m2d*Z[105+k] + m2e*Z[110+k];
            row[256 + v*5 + k] = __float2half(w2*in2 + w5*in5 + w7*in7 + w10*in10);
        }
    }
}

// ---------------- node mid: CSR gather (fp16), dn, squares, write cats ----------------
#define NPB 2
__global__ void node_mid(const float* __restrict__ W_down) {
    const int NT = 160;
    int n0 = blockIdx.x * NPB;
    int t = threadIdx.x;
    __shared__ __align__(16) float sh_agg[NPB][FEAT];
    __shared__ __align__(16) float sh_dn[NPB][FEAT];
    __shared__ __align__(16) float sh_cat0[NPB][256];
    __shared__ __align__(16) float sh_cat1[NPB][576];
    __shared__ __align__(16) float sh_cat2[NPB][1280];
    __shared__ __align__(16) float s_cg[1375];

    // gather: 4-half groups, accumulate fp32
    for (int i = t; i < 144 * NPB; i += NT) {
        int nn = i / 144, q = i - 144 * nn;
        int n = n0 + nn;
        int beg = g_off[n], end = g_off[n + 1];
        float4 a = make_float4(0.f, 0.f, 0.f, 0.f);
        for (int d = beg; d < end; d++) {
            int eid = g_elist[d];
            const __half2* hp = (const __half2*)(g_wo + (size_t)eid * 576 + q * 4);
            float2 p0 = __half22float2(hp[0]);
            float2 p1 = __half22float2(hp[1]);
            a.x += p0.x; a.y += p0.y; a.z += p1.x; a.w += p1.y;
        }
        ((float4*)sh_agg[nn])[q] = a;
    }
    for (int i = t; i < 1375; i += NT) s_cg[i] = g_cg[i];
    __syncthreads();

    // dn
    const float dn_scale = 0.125f * 0.3535533905932738f;
    for (int item = t; item < 144; item += NT) {
        int l, i, vg, off, d;
        decode_item(item, l, i, vg, off, d);
        const float4* W4 = (const float4*)(W_down + l * 4096) + vg;
        float4 acc[NPB];
        #pragma unroll
        for (int nn = 0; nn < NPB; nn++) acc[nn] = make_float4(0.f,0.f,0.f,0.f);
        #pragma unroll 4
        for (int u = 0; u < 64; u++) {
            float4 w = W4[u * 16];
            #pragma unroll
            for (int nn = 0; nn < NPB; nn++) {
                float f = sh_agg[nn][off + u * d + i];
                acc[nn].x += f*w.x; acc[nn].y += f*w.y;
                acc[nn].z += f*w.z; acc[nn].w += f*w.w;
            }
        }
        int v0 = vg * 4;
        #pragma unroll
        for (int nn = 0; nn < NPB; nn++) {
            float4 a = acc[nn];
            a.x *= dn_scale; a.y *= dn_scale; a.z *= dn_scale; a.w *= dn_scale;
            if (l == 0) { a.x = gelu_t(a.x); a.y = gelu_t(a.y); a.z = gelu_t(a.z); a.w = gelu_t(a.w); }
            sh_dn[nn][off + (v0+0)*d + i] = a.x;
            sh_dn[nn][off + (v0+1)*d + i] = a.y;
            sh_dn[nn][off + (v0+2)*d + i] = a.z;
            sh_dn[nn][off + (v0+3)*d + i] = a.w;
        }
    }
    __syncthreads();

    // cat dn parts
    for (int i = t; i < 64 * NPB; i += NT)  { int nn = i >> 6, r = i & 63; sh_cat0[nn][r] = sh_dn[nn][r]; }
    for (int i = t; i < 192 * NPB; i += NT) { int nn = i / 192, r = i - 192*nn; sh_cat1[nn][r] = sh_dn[nn][64 + r]; }
    for (int i = t; i < 320 * NPB; i += NT) { int nn = i / 320, r = i - 320*nn; sh_cat2[nn][r] = sh_dn[nn][256 + r]; }

    // squares
    {
        const int sq_cg[8]  = {0, 4, 9, 1, 6, 2, 5, 10};
        const int sq_lA[8]  = {0, 1, 2, 0, 1, 0, 1, 2};
        const int sq_lB[8]  = {0, 1, 2, 1, 2, 2, 1, 2};
        const int sq_lO[8]  = {0, 0, 0, 1, 1, 2, 2, 2};
        const int sq_blk[8] = {1, 2, 3, 1, 2, 1, 2, 3};
        const int loff[3] = {0, 64, 256};
        #pragma unroll
        for (int sp = 0; sp < 8; sp++) {
            int lA = sq_lA[sp], lB = sq_lB[sp], lO = sq_lO[sp];
            int dA = 2*lA+1, dB = 2*lB+1, dO = 2*lO+1;
            int offA = loff[lA], offB = loff[lB];
            const float* cgp = s_cg + sq_cg[sp] * 125;
            int nout = 64 * dO;
            int blk = sq_blk[sp];
            for (int idx = t; idx < nout; idx += NT) {
                int u = idx / dO, k = idx - dO * u;
                float accs[NPB] = {0.f, 0.f};
                #pragma unroll
                for (int i = 0; i < dA; i++) {
                    #pragma unroll
                    for (int j = 0; j < dB; j++) {
                        float cgv = cgp[(i*5 + j)*5 + k];
                        #pragma unroll
                        for (int nn = 0; nn < NPB; nn++)
                            accs[nn] += sh_dn[nn][offA + u*dA + i]
                                      * sh_dn[nn][offB + u*dB + j] * cgv;
                    }
                }
                #pragma unroll
                for (int nn = 0; nn < NPB; nn++) {
                    if (lO == 0)      sh_cat0[nn][blk*64 + u] = accs[nn];
                    else if (lO == 1) sh_cat1[nn][(blk*64 + u)*3 + k] = accs[nn];
                    else              sh_cat2[nn][(blk*64 + u)*5 + k] = accs[nn];
                }
            }
        }
    }
    __syncthreads();

    // write cats in GEMM-row layout
    for (int idx = t; idx < NPB * 256; idx += NT) {
        int nn = idx >> 8, u = idx & 255;
        g_cat0[(size_t)(n0 + nn) * 256 + u] = sh_cat0[nn][u];
    }
    for (int idx = t; idx < NPB * 576; idx += NT) {
        int nn = idx / 576, r = idx - 576 * nn;
        int i = r / 192, u = r - 192 * i;
        g_cat1[((size_t)(n0 + nn) * 3 + i) * 192 + u] = sh_cat1[nn][u*3 + i];
    }
    for (int idx = t; idx < NPB * 1280; idx += NT) {
        int nn = idx / 1280, r = idx - 1280 * nn;
        int i = r / 256, u = r - 256 * i;
        g_cat2[((size_t)(n0 + nn) * 5 + i) * 256 + u] = sh_cat2[nn][u*5 + i];
    }
}

// ---------------- W_out GEMM (TF32) ----------------
__global__ void wout_gemm_tf32(int l, int rows, int K, int woff, float scale) {
    int r0 = blockIdx.x * 64;
    int t = threadIdx.x;
    int wi = t >> 5;
    int lane = t & 31;
    int g = lane >> 2;
    int c = lane & 3;

    const float* cat = (l == 0) ? g_cat0 : ((l == 1) ? g_cat1 : g_cat2);

    __shared__ __align__(16) uint32_t s_a[64][68];
    __shared__ __align__(16) uint32_t s_b[64][72];

    float acc[8][4];
    #pragma unroll
    for (int nt = 0; nt < 8; nt++)
        #pragma unroll
        for (int q = 0; q < 4; q++) acc[nt][q] = 0.0f;

    int eb = wi * 16;
    int nchunks = K >> 6;
    for (int kc = 0; kc < nchunks; kc++) {
        if (kc > 0) __syncthreads();
        #pragma unroll
        for (int it = 0; it < 8; it++) {
            int idx = t + it * 128;
            int r = idx >> 4, k4 = idx & 15;
            int row = r0 + r;
            uint32_t* dst = &s_a[r][k4 * 4];
            if (row < rows) {
                float4 v = ((const float4*)(cat + (size_t)row * K + kc * 64))[k4];
                dst[0] = f2tf32(v.x); dst[1] = f2tf32(v.y);
                dst[2] = f2tf32(v.z); dst[3] = f2tf32(v.w);
            } else {
                dst[0] = 0; dst[1] = 0; dst[2] = 0; dst[3] = 0;
            }
        }
        #pragma unroll
        for (int it = 0; it < 8; it++) {
            int idx = t + it * 128;
            int k = idx >> 4, o4 = idx & 15;
            uint4 v = ((const uint4*)(g_wt + (size_t)woff + (size_t)(kc * 64 + k) * 64))[o4];
            *(uint4*)&s_b[k][o4 * 4] = v;
        }
        __syncthreads();

        #pragma unroll
        for (int ks = 0; ks < 8; ks++) {
            int kb = ks * 8;
            uint32_t a0 = s_a[eb + g][kb + c];
            uint32_t a1 = s_a[eb + g + 8][kb + c];
            uint32_t a2 = s_a[eb + g][kb + c + 4];
            uint32_t a3 = s_a[eb + g + 8][kb + c + 4];
            #pragma unroll
            for (int nt = 0; nt < 8; nt++) {
                uint32_t b0 = s_b[kb + c][nt * 8 + g];
                uint32_t b1 = s_b[kb + c + 4][nt * 8 + g];
                asm volatile(
                    "mma.sync.aligned.m16n8k8.row.col.f32.tf32.tf32.f32 "
                    "{%0,%1,%2,%3}, {%4,%5,%6,%7}, {%8,%9}, {%0,%1,%2,%3};"
                    : "+f"(acc[nt][0]), "+f"(acc[nt][1]), "+f"(acc[nt][2]), "+f"(acc[nt][3])
                    : "r"(a0), "r"(a1), "r"(a2), "r"(a3), "r"(b0), "r"(b1));
            }
        }
    }

    int er0 = r0 + eb + g;
    int er1 = er0 + 8;
    #pragma unroll
    for (int nt = 0; nt < 8; nt++) {
        int col = nt * 8 + 2 * c;
        #pragma unroll
        for (int h = 0; h < 2; h++) {
            int row = (h == 0) ? er0 : er1;
            if (row >= rows) continue;
            float va = acc[nt][h * 2 + 0] * scale;
            float vb = acc[nt][h * 2 + 1] * scale;
            size_t addr;
            if (l == 0) {
                addr = (size_t)row * FEAT + col;
                g_o[addr] = va; g_o[addr + 1] = vb;
            } else if (l == 1) {
                int n = row / 3, i = row - 3 * n;
                addr = (size_t)n * FEAT + 64 + (size_t)col * 3 + i;
                g_o[addr] = va; g_o[addr + 3] = vb;
            } else {
                int n = row / 5, i = row - 5 * n;
                addr = (size_t)n * FEAT + 256 + (size_t)col * 5 + i;
                g_o[addr] = va; g_o[addr + 5] = vb;
            }
        }
    }
}

// ---------------- node fin: softnorm + skip combine ----------------
__global__ void node_fin(float* __restrict__ out, int n_nodes) {
    int idx = blockIdx.x * 256 + threadIdx.x;
    int total = n_nodes * 192;
    if (idx >= total) return;
    int n = idx / 192, gq = idx - 192 * n;
    int l = gq >> 6, v = gq & 63;
    int off = (l == 0) ? 0 : ((l == 1) ? 64 : 256);
    int d = 2 * l + 1;
    size_t base = (size_t)n * FEAT + off + (size_t)v * d;
    float vals[5];
    float s2 = 0.0f;
    for (int j = 0; j < d; j++) { vals[j] = g_o[base + j]; s2 += vals[j] * vals[j]; }
    float nrm = sqrtf(s2) * 1e-5f;
    float sus = (nrm > 0.0f) ? expf(-1.0f / nrm) : 0.0f;
    float inv = 1.0f / (1.0f + nrm * sus);
    for (int j = 0; j < d; j++) {
        out[base + j] = 0.9f * g_skip[base + j] + 0.45f * vals[j] * inv;
    }
}

// ---------------- launch ----------------
extern "C" void kernel_launch(void* const* d_in, const int* in_sizes, int n_in,
                              void* d_out, int out_size) {
    const float* vectors    = (const float*)d_in[0];
    const float* node_feats = (const float*)d_in[1];
    const float* W_up       = (const float*)d_in[2];
    const float* W_skip     = (const float*)d_in[3];
    const float* M1         = (const float*)d_in[4];
    const float* M2         = (const float*)d_in[5];
    const float* M3         = (const float*)d_in[6];
    const float* W_out0     = (const float*)d_in[7];
    const float* W_out1     = (const float*)d_in[8];
    const float* W_out2     = (const float*)d_in[9];
    const float* W_down     = (const float*)d_in[10];
    const int*   specie     = (const int*)d_in[11];
    const int*   senders    = (const int*)d_in[12];
    const int*   receivers  = (const int*)d_in[13];

    int n_nodes = in_sizes[11];
    int n_edges = in_sizes[12];

    cg_kernel<<<11, 128>>>();
    prep<<<(45056 + 255) / 256, 256>>>(M3, W_out0, W_out1, W_out2);
    hist<<<(n_edges + 255) / 256, 256>>>(receivers, n_edges);
    scan_kernel<<<1, 1024>>>();
    scatter_ids<<<(n_edges + 255) / 256, 256>>>(receivers, n_edges);
    node_pre<<<n_nodes, 160>>>(node_feats, W_up, W_skip, specie);
    edge_basis<<<n_edges / 32, 256>>>(vectors, M1, M2);
    w_gemm_tf32<<<n_edges / 64, 128>>>();
    edge_tp<<<n_edges / 8, 256>>>(vectors, senders);
    node_mid<<<n_nodes / NPB, 160>>>(W_down);
    {
        int r0 = n_nodes;
        int r1 = n_nodes * 3;
        int r2 = n_nodes * 5;
        wout_gemm_tf32<<<(r0 + 63) / 64, 128>>>(0, r0, 256, 0,     0.0625f);
        wout_gemm_tf32<<<(r1 + 63) / 64, 128>>>(1, r1, 192, 16384, 0.07216878364870323f);
        wout_gemm_tf32<<<(r2 + 63) / 64, 128>>>(2, r2, 256, 28672, 0.0625f);
    }
    node_fin<<<(n_nodes * 192 + 255) / 256, 256>>>((float*)d_out, n_nodes);
}